// round 9
// baseline (speedup 1.0000x reference)
#include <cuda_runtime.h>
#include <cuda_bf16.h>
#include <cstdint>
#include <math.h>

// ---------------------------------------------------------------------------
// Q6Model: 2-layer ConvLSTM (T=10) + dense head + concat + FC head
// Round 9: mma.sync bf16 path, warp tile 64x64 (BN=256), ldmatrix fragment
// loads (n-major weights), fused LSTM epilogue, ping-pong h. 28 launches.
// ---------------------------------------------------------------------------

#define H1N (8*30*30*256)
#define H2N (8*28*28*128)

__device__ __nv_bfloat16 g_h1b[2][H1N];
__device__ float         g_c1[H1N];
__device__ __nv_bfloat16 g_h2b[2][H2N];
__device__ float         g_c2[H2N];
__device__ float         g_h2f[H2N];
__device__ float g_scr256[8*28*28*256];
__device__ float g_dh[8*28*28*64];
// n-major bf16 weights: [tap][n'][k], n' = 4*(n%F)+n/F (gate-interleaved)
__device__ __nv_bfloat16 g_Wt1[9*1024*256];
__device__ __nv_bfloat16 g_Wt2x[9*512*256];
__device__ __nv_bfloat16 g_Wt2h[9*512*128];
// gate-interleaved fp32 x-conv weights
__device__ float g_Wx1i[9*1024];

__global__ void zero_state_kernel() {
    int i = blockIdx.x * blockDim.x + threadIdx.x;
    int stride = gridDim.x * blockDim.x;
    unsigned* h1u = (unsigned*)g_h1b;
    unsigned* h2u = (unsigned*)g_h2b;
    for (int k = i; k < H1N; k += stride) g_c1[k] = 0.f;
    for (int k = i; k < H1N; k += stride) h1u[k] = 0u;  // 2 bufs * H1N bf16 = H1N u32
    for (int k = i; k < H2N; k += stride) g_c2[k] = 0.f;
    for (int k = i; k < H2N; k += stride) h2u[k] = 0u;
}

// out[(tap*N + np)*C + k] = bf16( W[(tap*C + k)*N + n] ), np = 4*(n%F)+n/F
__global__ void pack_wt_kernel(const float* __restrict__ W, __nv_bfloat16* __restrict__ out,
                               int C, int N, int total)
{
    int i = blockIdx.x * blockDim.x + threadIdx.x;
    int stride = gridDim.x * blockDim.x;
    int F = N >> 2;
    for (int idx = i; idx < total; idx += stride) {
        int k = idx % C;
        int r = idx / C;
        int np = r % N;
        int tap = r / N;
        int g = np & 3, f = np >> 2;
        int n = g * F + f;
        out[idx] = __float2bfloat16(W[(long)(tap * C + k) * N + n]);
    }
}

// in[t][n] fp32 -> out[t][n'] fp32
__global__ void interleave_kernel(const float* __restrict__ W, float* __restrict__ out,
                                  int N, int total)
{
    int i = blockIdx.x * blockDim.x + threadIdx.x;
    int stride = gridDim.x * blockDim.x;
    int F = N >> 2;
    for (int idx = i; idx < total; idx += stride) {
        int n = idx % N;
        int t = idx / N;
        int np = 4 * (n % F) + (n / F);
        out[t * N + np] = W[idx];
    }
}

__device__ __forceinline__ void mma_bf16(float* d, const unsigned* a, const unsigned* b) {
    asm volatile(
        "mma.sync.aligned.m16n8k16.row.col.f32.bf16.bf16.f32 "
        "{%0,%1,%2,%3}, {%4,%5,%6,%7}, {%8,%9}, {%0,%1,%2,%3};\n"
        : "+f"(d[0]), "+f"(d[1]), "+f"(d[2]), "+f"(d[3])
        : "r"(a[0]), "r"(a[1]), "r"(a[2]), "r"(a[3]), "r"(b[0]), "r"(b[1]));
}

__device__ __forceinline__ void ldsm_x4(unsigned& r0, unsigned& r1, unsigned& r2, unsigned& r3,
                                        unsigned addr) {
    asm volatile("ldmatrix.sync.aligned.m8n8.x4.shared.b16 {%0,%1,%2,%3}, [%4];"
                 : "=r"(r0), "=r"(r1), "=r"(r2), "=r"(r3) : "r"(addr));
}

__device__ __forceinline__ void cp16(unsigned dst, const void* src, int sz) {
    asm volatile("cp.async.cg.shared.global [%0], [%1], 16, %2;"
                 :: "r"(dst), "l"(src), "r"(sz));
}

__device__ __forceinline__ float sigmoidf_(float x) { return 1.f / (1.f + expf(-x)); }

// ---------------------------------------------------------------------------
// Fused conv-gates GEMM + LSTM update.
// BM=128, BN=256, BK=32 bf16. 256 threads = 8 warps (2M x 4N), warp 64x64.
// A tile: 128 rows x 64B (stride 80B). B tile: 256 n-rows x 64B (stride 80B).
// 4-buffer cp.async ring, one __syncthreads per tile.
// Fragments via ldmatrix.x4 (conflict-free with 80B stride).
// ---------------------------------------------------------------------------
#define BM 128
#define BN 256
#define BK 32
#define ROWB 80
#define A_TILE (BM*ROWB)                   // 10240
#define B_TILE (BN*ROWB)                   // 20480
#define STAGE_B (A_TILE + B_TILE)          // 30720
#define NBUF 4
#define SROW2 65
#define SG (128*SROW2)
#define S_BYTES (4*SG*4)                   // 133120
#define DSMEM_ALLOC (S_BYTES)              // > NBUF*STAGE_B (122880)

__global__ __launch_bounds__(256)
void conv_lstm_kernel(
    const __nv_bfloat16* __restrict__ srcA, int CA, int HA, int WA, long sAb, int padA,
    const __nv_bfloat16* __restrict__ WtA, int kt0,
    const __nv_bfloat16* __restrict__ srcB, int CB, long sBb,
    const __nv_bfloat16* __restrict__ WtB, int kt1,
    const float* __restrict__ xsrc, int xW, long xsb,
    const float* __restrict__ WxI, int useX,
    const float* __restrict__ bias,
    __nv_bfloat16* __restrict__ hb, float* __restrict__ hf,
    float* __restrict__ c,
    int OH, int OW, int N, int M)
{
    extern __shared__ char smem[];
    unsigned smem_u = (unsigned)__cvta_generic_to_shared(smem);

    const int tid = threadIdx.x;
    const int m0 = blockIdx.x * BM;
    const int n0 = blockIdx.y * BN;

    const int wid = tid >> 5, lane = tid & 31;
    const int wm = (wid >> 2) * 64;       // 2 warp rows
    const int wn = (wid & 3) * 64;        // 4 warp cols
    const int g = lane >> 2, tg = lane & 3;

    // ldmatrix lane-derived address components
    const int a_lrow = lane & 15;
    const int a_koff = (lane & 16) ? 16 : 0;
    const int b_lrow = (lane & 7) + ((lane & 16) ? 8 : 0);
    const int b_koff = (lane & 8) ? 16 : 0;

    // staging coords
    const int arow = tid >> 1;            // A row 0..127
    const int ahalf = tid & 1;            // 32B half

    int s_pb = 0, s_py = 0, s_px = 0;
    bool s_valid;
    {
        int gm = m0 + arow;
        s_valid = gm < M;
        int r = s_valid ? gm : 0;
        s_px = r % OW; r /= OW;
        s_py = r % OH; s_pb = r / OH;
    }

    const int nt0 = 9 * kt0;
    const int ntiles = nt0 + 9 * kt1;

    float acc[4][8][4];
#pragma unroll
    for (int mi = 0; mi < 4; ++mi)
#pragma unroll
        for (int ni = 0; ni < 8; ++ni)
#pragma unroll
            for (int r = 0; r < 4; ++r) acc[mi][ni][r] = 0.f;

    auto stage = [&](int t, int buf) {
        int tap, K0, C, H, W, pad;
        long sb;
        const __nv_bfloat16 *src, *Wt;
        if (t < nt0) {
            tap = t / kt0; K0 = (t - tap * kt0) * BK;
            src = srcA; Wt = WtA; C = CA; H = HA; W = WA; sb = sAb; pad = padA;
        } else {
            int u = t - nt0;
            tap = u / kt1; K0 = (u - tap * kt1) * BK;
            src = srcB; Wt = WtB; C = CB; H = OH; W = OW; sb = sBb; pad = 1;
        }
        int y = s_py + tap / 3 - pad;
        int x = s_px + tap % 3 - pad;
        bool ok = s_valid && ((unsigned)y < (unsigned)H) && ((unsigned)x < (unsigned)W);
        const __nv_bfloat16* ap = ok
            ? src + (long)s_pb * sb + ((long)y * W + x) * C + K0 + ahalf * 16
            : src;
        int sz = ok ? 16 : 0;
        unsigned da = smem_u + buf * STAGE_B + arow * ROWB + ahalf * 32;
        cp16(da, ap, sz);
        cp16(da + 16, ap + 8, sz);
        // B: one n-row per thread (256 rows), 64B = 4x16B
        const __nv_bfloat16* bp = Wt + ((long)tap * N + n0 + tid) * C + K0;
        unsigned db = smem_u + buf * STAGE_B + A_TILE + tid * ROWB;
#pragma unroll
        for (int q = 0; q < 4; ++q) cp16(db + q * 16, bp + q * 8, 16);
    };

    auto compute = [&](int buf) {
        unsigned Ab = smem_u + buf * STAGE_B;
        unsigned Bb = Ab + A_TILE;
#pragma unroll
        for (int ks = 0; ks < 2; ++ks) {
            unsigned a[4][4];
#pragma unroll
            for (int mi = 0; mi < 4; ++mi)
                ldsm_x4(a[mi][0], a[mi][1], a[mi][2], a[mi][3],
                        Ab + (unsigned)((wm + mi * 16 + a_lrow) * ROWB + a_koff + ks * 32));
            unsigned b[8][2];
#pragma unroll
            for (int np = 0; np < 4; ++np) {
                unsigned r0, r1, r2, r3;
                ldsm_x4(r0, r1, r2, r3,
                        Bb + (unsigned)((wn + np * 16 + b_lrow) * ROWB + b_koff + ks * 32));
                b[2 * np][0] = r0; b[2 * np][1] = r1;
                b[2 * np + 1][0] = r2; b[2 * np + 1][1] = r3;
            }
#pragma unroll
            for (int mi = 0; mi < 4; ++mi)
#pragma unroll
                for (int ni = 0; ni < 8; ++ni)
                    mma_bf16(acc[mi][ni], a[mi], b[ni]);
        }
    };

    // ---- 4-buffer pipelined main loop (one sync per tile) ----
    stage(0, 0);
    asm volatile("cp.async.commit_group;");
    stage(1, 1);
    asm volatile("cp.async.commit_group;");
    for (int t = 0; t < ntiles; ++t) {
        if (t + 2 < ntiles) {
            stage(t + 2, (t + 2) & 3);
            asm volatile("cp.async.commit_group;");
            asm volatile("cp.async.wait_group 2;");
        } else if (t + 1 < ntiles) {
            asm volatile("cp.async.wait_group 1;");
        } else {
            asm volatile("cp.async.wait_group 0;");
        }
        __syncthreads();
        compute(t & 3);
    }

    // ---- fp32 epilogue for the C=1 input conv (layer 1 only), interleaved W
    if (useX) {
        int epb[8], epy[8], epx[8];
        bool ev[8];
#pragma unroll
        for (int e = 0; e < 8; ++e) {
            int rr = m0 + wm + (e >> 1) * 16 + g + (e & 1) * 8;
            ev[e] = rr < M;
            int r2 = ev[e] ? rr : 0;
            epx[e] = r2 % OW; r2 /= OW;
            epy[e] = r2 % OH; epb[e] = r2 / OH;
        }
        for (int tap = 0; tap < 9; ++tap) {
            int dy = tap / 3, dx = tap % 3;   // VALID: pad 0
            float wv[8][2];
#pragma unroll
            for (int ni = 0; ni < 8; ++ni) {
                int col = n0 + wn + ni * 8 + 2 * tg;
                wv[ni][0] = WxI[tap * N + col];
                wv[ni][1] = WxI[tap * N + col + 1];
            }
#pragma unroll
            for (int e = 0; e < 8; ++e) if (ev[e]) {
                float xv = xsrc[(long)epb[e] * xsb + (long)(epy[e] + dy) * xW + (epx[e] + dx)];
#pragma unroll
                for (int ni = 0; ni < 8; ++ni) {
                    acc[e >> 1][ni][(e & 1) * 2 + 0] = fmaf(xv, wv[ni][0], acc[e >> 1][ni][(e & 1) * 2 + 0]);
                    acc[e >> 1][ni][(e & 1) * 2 + 1] = fmaf(xv, wv[ni][1], acc[e >> 1][ni][(e & 1) * 2 + 1]);
                }
            }
        }
    }

    // ---- fused LSTM epilogue ----
    __syncthreads();                       // all ring-buffer reads done
    float* S = (float*)smem;
#pragma unroll
    for (int mi = 0; mi < 4; ++mi) {
#pragma unroll
        for (int ni = 0; ni < 8; ++ni) {
            int c0 = wn + ni * 8 + 2 * tg;     // local interleaved col (even)
            int c1 = c0 + 1;
            int r0 = wm + mi * 16 + g;
            int r1 = r0 + 8;
            S[(c0 & 3) * SG + r0 * SROW2 + (c0 >> 2)] = acc[mi][ni][0];
            S[(c1 & 3) * SG + r0 * SROW2 + (c1 >> 2)] = acc[mi][ni][1];
            S[(c0 & 3) * SG + r1 * SROW2 + (c0 >> 2)] = acc[mi][ni][2];
            S[(c1 & 3) * SG + r1 * SROW2 + (c1 >> 2)] = acc[mi][ni][3];
        }
    }
    __syncthreads();

    {
        const int F = N >> 2;
        const int fl = tid & 63;           // feature lane (64 feats per block)
        const int rgrp = tid >> 6;         // 4 row groups x 32 rows
        const int fg = (n0 >> 2) + fl;
        const float bi = bias[fg];
        const float bfr = bias[F + fg];
        const float bc = bias[2 * F + fg];
        const float bo = bias[3 * F + fg];
#pragma unroll 4
        for (int j = 0; j < 32; ++j) {
            int r = rgrp * 32 + j;
            int gm = m0 + r;
            if (gm < M) {
                float zi = S[0 * SG + r * SROW2 + fl] + bi;
                float zf = S[1 * SG + r * SROW2 + fl] + bfr;
                float zc = S[2 * SG + r * SROW2 + fl] + bc;
                float zo = S[3 * SG + r * SROW2 + fl] + bo;
                long ci = (long)gm * F + fg;
                float cn = sigmoidf_(zf) * c[ci] + sigmoidf_(zi) * tanhf(zc);
                float hn = sigmoidf_(zo) * tanhf(cn);
                c[ci] = cn;
                hb[ci] = __float2bfloat16(hn);
                if (hf) hf[ci] = hn;
            }
        }
    }
}

// ---------------------------------------------------------------------------
__global__ void dense_relu_kernel(const float* __restrict__ in,
                                  const float* __restrict__ W,
                                  const float* __restrict__ bias,
                                  float* __restrict__ out,
                                  int M, int K, int N, int do_relu)
{
    int idx = blockIdx.x * blockDim.x + threadIdx.x;
    if (idx >= M * N) return;
    int m = idx / N, n = idx % N;
    const float* ip = in + (long)m * K;
    float s = bias[n];
    for (int k = 0; k < K; ++k) s = fmaf(ip[k], W[k * N + n], s);
    if (do_relu) s = fmaxf(s, 0.f);
    out[idx] = s;
}

// ---------------------------------------------------------------------------
__global__ void final_fc_kernel(const float* __restrict__ dh,
                                const float* __restrict__ tin,
                                const float* __restrict__ locin,
                                const float* __restrict__ Wf1,
                                const float* __restrict__ bf1,
                                const float* __restrict__ Wf2,
                                const float* __restrict__ bf2,
                                float* __restrict__ out)
{
    int blk = blockIdx.x;              // = (b*30 + r)*28 + w
    int w = blk % 28;
    int r = (blk / 28) % 30;
    int b = blk / (28 * 30);

    __shared__ float v[64];
    __shared__ float red[64];
    int j = threadIdx.x;

    const float* src;
    if (r < 28)       src = dh    + (((long)(b * 28 + r)) * 28 + w) * 64;
    else if (r == 28) src = tin   + ((long)b * 28 + w) * 64;
    else              src = locin + ((long)b * 28 + w) * 64;
    v[j] = src[j];
    __syncthreads();

    float s = bf1[j];
#pragma unroll
    for (int k = 0; k < 64; ++k) s = fmaf(v[k], Wf1[k * 64 + j], s);
    s = fmaxf(s, 0.f) * Wf2[j];
    red[j] = s;
    __syncthreads();
    for (int off = 32; off > 0; off >>= 1) {
        if (j < off) red[j] += red[j + off];
        __syncthreads();
    }
    if (j == 0) out[blk] = red[0] + bf2[0];
}

// ---------------------------------------------------------------------------
extern "C" void kernel_launch(void* const* d_in, const int* in_sizes, int n_in,
                              void* d_out, int out_size)
{
    const float* x   = (const float*)d_in[0];
    const float* tt  = (const float*)d_in[1];
    const float* loc = (const float*)d_in[2];
    const float* Wx1 = (const float*)d_in[3];
    const float* Wh1 = (const float*)d_in[4];
    const float* b1  = (const float*)d_in[5];
    const float* Wx2 = (const float*)d_in[6];
    const float* Wh2 = (const float*)d_in[7];
    const float* b2  = (const float*)d_in[8];
    const float* Wd1 = (const float*)d_in[9];
    const float* bd1 = (const float*)d_in[10];
    const float* Wd2 = (const float*)d_in[11];
    const float* bd2 = (const float*)d_in[12];
    const float* Wf1 = (const float*)d_in[13];
    const float* bf1 = (const float*)d_in[14];
    const float* Wf2 = (const float*)d_in[15];
    const float* bf2 = (const float*)d_in[16];
    float* out = (float*)d_out;

    __nv_bfloat16 *h1b0, *h1b1, *h2b0, *h2b1, *Wt1, *Wt2x, *Wt2h;
    float *c1, *c2, *h2f, *scr256, *dh, *Wx1i;
    cudaGetSymbolAddress((void**)&h1b0, g_h1b);  h1b1 = h1b0 + H1N;
    cudaGetSymbolAddress((void**)&h2b0, g_h2b);  h2b1 = h2b0 + H2N;
    cudaGetSymbolAddress((void**)&c1, g_c1);
    cudaGetSymbolAddress((void**)&c2, g_c2);
    cudaGetSymbolAddress((void**)&h2f, g_h2f);
    cudaGetSymbolAddress((void**)&scr256, g_scr256);
    cudaGetSymbolAddress((void**)&dh, g_dh);
    cudaGetSymbolAddress((void**)&Wt1, g_Wt1);
    cudaGetSymbolAddress((void**)&Wt2x, g_Wt2x);
    cudaGetSymbolAddress((void**)&Wt2h, g_Wt2h);
    cudaGetSymbolAddress((void**)&Wx1i, g_Wx1i);

    cudaFuncSetAttribute(conv_lstm_kernel,
                         cudaFuncAttributeMaxDynamicSharedMemorySize, DSMEM_ALLOC);

    zero_state_kernel<<<1024, 256>>>();
    pack_wt_kernel<<<2048, 256>>>(Wh1, Wt1, 256, 1024, 9 * 1024 * 256);
    pack_wt_kernel<<<1024, 256>>>(Wx2, Wt2x, 256, 512, 9 * 512 * 256);
    pack_wt_kernel<<<512, 256>>>(Wh2, Wt2h, 128, 512, 9 * 512 * 128);
    interleave_kernel<<<36, 256>>>(Wx1, Wx1i, 1024, 9 * 1024);

    const int M1 = 8 * 30 * 30;   // 7200
    const int M2 = 8 * 28 * 28;   // 6272

    for (int ts = 0; ts < 10; ++ts) {
        int p = ts & 1;
        __nv_bfloat16* h1r = p ? h1b1 : h1b0;
        __nv_bfloat16* h1w = p ? h1b0 : h1b1;
        __nv_bfloat16* h2r = p ? h2b1 : h2b0;
        __nv_bfloat16* h2w = p ? h2b0 : h2b1;

        // L1: recurrent conv (h1r, SAME, C=256) + x-conv epilogue + LSTM -> h1w
        conv_lstm_kernel<<<dim3((M1 + BM - 1) / BM, 1024 / BN), 256, DSMEM_ALLOC>>>(
            h1r, 256, 30, 30, (long)30 * 30 * 256, 1, Wt1, /*kt0=*/0,
            h1r, 256, (long)30 * 30 * 256, Wt1, /*kt1=*/8,
            x + (long)ts * 32 * 32, 32, (long)10 * 32 * 32, Wx1i, /*useX=*/1,
            b1, h1w, nullptr, c1, 30, 30, 1024, M1);

        // L2: input conv (h1w, VALID, C=256) + recurrent conv (h2r, SAME, C=128) + LSTM -> h2w
        conv_lstm_kernel<<<dim3((M2 + BM - 1) / BM, 512 / BN), 256, DSMEM_ALLOC>>>(
            h1w, 256, 30, 30, (long)30 * 30 * 256, 0, Wt2x, /*kt0=*/8,
            h2r, 128, (long)28 * 28 * 128, Wt2h, /*kt1=*/4,
            x, 32, (long)10 * 32 * 32, Wx1i, /*useX=*/0,
            b2, h2w, h2f, c2, 28, 28, 512, M2);
    }

    dense_relu_kernel<<<(M2 * 256 + 255) / 256, 256>>>(h2f, Wd1, bd1, scr256, M2, 128, 256, 1);
    dense_relu_kernel<<<(M2 * 64 + 255) / 256, 256>>>(scr256, Wd2, bd2, dh, M2, 256, 64, 1);

    final_fc_kernel<<<8 * 30 * 28, 64>>>(dh, tt, loc, Wf1, bf1, Wf2, bf2, out);
}

// round 10
// speedup vs baseline: 1.2666x; 1.2666x over previous
#include <cuda_runtime.h>
#include <cuda_bf16.h>
#include <cstdint>
#include <math.h>

// ---------------------------------------------------------------------------
// Q6Model: 2-layer ConvLSTM (T=10) + dense head + concat + FC head
// Round 10 = R7 tile economy (BM=128,BN=128,BK=32, warp 64x32, 2 CTA/SM)
//          + R9's verified ldmatrix fragment loads (n-major bf16 weights).
// Fused LSTM epilogue, ping-pong h, 4-buffer cp.async ring. 28 launches.
// ---------------------------------------------------------------------------

#define H1N (8*30*30*256)
#define H2N (8*28*28*128)

__device__ __nv_bfloat16 g_h1b[2][H1N];
__device__ float         g_c1[H1N];
__device__ __nv_bfloat16 g_h2b[2][H2N];
__device__ float         g_c2[H2N];
__device__ float         g_h2f[H2N];
__device__ float g_scr256[8*28*28*256];
__device__ float g_dh[8*28*28*64];
// n-major bf16 weights: [tap][n'][k], n' = 4*(n%F)+n/F (gate-interleaved)
__device__ __nv_bfloat16 g_Wt1[9*1024*256];
__device__ __nv_bfloat16 g_Wt2x[9*512*256];
__device__ __nv_bfloat16 g_Wt2h[9*512*128];
// gate-interleaved fp32 x-conv weights
__device__ float g_Wx1i[9*1024];

__global__ void zero_state_kernel() {
    int i = blockIdx.x * blockDim.x + threadIdx.x;
    int stride = gridDim.x * blockDim.x;
    unsigned* h1u = (unsigned*)g_h1b;
    unsigned* h2u = (unsigned*)g_h2b;
    for (int k = i; k < H1N; k += stride) g_c1[k] = 0.f;
    for (int k = i; k < H1N; k += stride) h1u[k] = 0u;  // 2 bufs * H1N bf16 = H1N u32
    for (int k = i; k < H2N; k += stride) g_c2[k] = 0.f;
    for (int k = i; k < H2N; k += stride) h2u[k] = 0u;
}

// out[(tap*N + np)*C + k] = bf16( W[(tap*C + k)*N + n] ), np = 4*(n%F)+n/F
__global__ void pack_wt_kernel(const float* __restrict__ W, __nv_bfloat16* __restrict__ out,
                               int C, int N, int total)
{
    int i = blockIdx.x * blockDim.x + threadIdx.x;
    int stride = gridDim.x * blockDim.x;
    int F = N >> 2;
    for (int idx = i; idx < total; idx += stride) {
        int k = idx % C;
        int r = idx / C;
        int np = r % N;
        int tap = r / N;
        int g = np & 3, f = np >> 2;
        int n = g * F + f;
        out[idx] = __float2bfloat16(W[(long)(tap * C + k) * N + n]);
    }
}

// in[t][n] fp32 -> out[t][n'] fp32
__global__ void interleave_kernel(const float* __restrict__ W, float* __restrict__ out,
                                  int N, int total)
{
    int i = blockIdx.x * blockDim.x + threadIdx.x;
    int stride = gridDim.x * blockDim.x;
    int F = N >> 2;
    for (int idx = i; idx < total; idx += stride) {
        int n = idx % N;
        int t = idx / N;
        int np = 4 * (n % F) + (n / F);
        out[t * N + np] = W[idx];
    }
}

__device__ __forceinline__ void mma_bf16(float* d, const unsigned* a, const unsigned* b) {
    asm volatile(
        "mma.sync.aligned.m16n8k16.row.col.f32.bf16.bf16.f32 "
        "{%0,%1,%2,%3}, {%4,%5,%6,%7}, {%8,%9}, {%0,%1,%2,%3};\n"
        : "+f"(d[0]), "+f"(d[1]), "+f"(d[2]), "+f"(d[3])
        : "r"(a[0]), "r"(a[1]), "r"(a[2]), "r"(a[3]), "r"(b[0]), "r"(b[1]));
}

__device__ __forceinline__ void ldsm_x4(unsigned& r0, unsigned& r1, unsigned& r2, unsigned& r3,
                                        unsigned addr) {
    asm volatile("ldmatrix.sync.aligned.m8n8.x4.shared.b16 {%0,%1,%2,%3}, [%4];"
                 : "=r"(r0), "=r"(r1), "=r"(r2), "=r"(r3) : "r"(addr));
}

__device__ __forceinline__ void cp16(unsigned dst, const void* src, int sz) {
    asm volatile("cp.async.cg.shared.global [%0], [%1], 16, %2;"
                 :: "r"(dst), "l"(src), "r"(sz));
}

__device__ __forceinline__ float sigmoidf_(float x) { return 1.f / (1.f + expf(-x)); }

// ---------------------------------------------------------------------------
// Fused conv-gates GEMM + LSTM update.
// BM=128, BN=128, BK=32 bf16. 256 threads = 8 warps (2M x 4N), warp 64x32.
// A tile: 128 m-rows x 64B (stride 80B). B tile: 128 n-rows x 64B (stride 80B).
// 4-buffer cp.async ring, one __syncthreads per tile. Fragments via ldmatrix.
// ---------------------------------------------------------------------------
#define BM 128
#define BN 128
#define BK 32
#define ROWB 80
#define A_TILE (BM*ROWB)                   // 10240
#define B_TILE (BN*ROWB)                   // 10240
#define STAGE_B (A_TILE + B_TILE)          // 20480
#define NBUF 4
#define SROW 33
#define SG (128*SROW)                      // 4224 words per gate plane
#define DSMEM_ALLOC (NBUF*STAGE_B)         // 81920 (> 4*SG*4 = 67584)

__global__ __launch_bounds__(256)
void conv_lstm_kernel(
    const __nv_bfloat16* __restrict__ srcA, int CA, int HA, int WA, long sAb, int padA,
    const __nv_bfloat16* __restrict__ WtA, int kt0,
    const __nv_bfloat16* __restrict__ srcB, int CB, long sBb,
    const __nv_bfloat16* __restrict__ WtB, int kt1,
    const float* __restrict__ xsrc, int xW, long xsb,
    const float* __restrict__ WxI, int useX,
    const float* __restrict__ bias,
    __nv_bfloat16* __restrict__ hb, float* __restrict__ hf,
    float* __restrict__ c,
    int OH, int OW, int N, int M)
{
    extern __shared__ char smem[];
    unsigned smem_u = (unsigned)__cvta_generic_to_shared(smem);

    const int tid = threadIdx.x;
    const int m0 = blockIdx.x * BM;
    const int n0 = blockIdx.y * BN;

    const int wid = tid >> 5, lane = tid & 31;
    const int wm = (wid >> 2) * 64;       // 2 warp rows (64 m each)
    const int wn = (wid & 3) * 32;        // 4 warp cols (32 n each)
    const int g = lane >> 2, tg = lane & 3;

    // ldmatrix lane-derived address components (validated in R9)
    const int a_lrow = lane & 15;
    const int a_koff = (lane & 16) ? 16 : 0;
    const int b_lrow = (lane & 7) + ((lane & 16) ? 8 : 0);
    const int b_koff = (lane & 8) ? 16 : 0;

    // staging coords (both tiles: row = tid>>1, 32B half = tid&1)
    const int arow = tid >> 1;
    const int ahalf = tid & 1;

    int s_pb = 0, s_py = 0, s_px = 0;
    bool s_valid;
    {
        int gm = m0 + arow;
        s_valid = gm < M;
        int r = s_valid ? gm : 0;
        s_px = r % OW; r /= OW;
        s_py = r % OH; s_pb = r / OH;
    }

    const int nt0 = 9 * kt0;
    const int ntiles = nt0 + 9 * kt1;

    float acc[4][4][4];
#pragma unroll
    for (int mi = 0; mi < 4; ++mi)
#pragma unroll
        for (int ni = 0; ni < 4; ++ni)
#pragma unroll
            for (int r = 0; r < 4; ++r) acc[mi][ni][r] = 0.f;

    auto stage = [&](int t, int buf) {
        int tap, K0, C, H, W, pad;
        long sb;
        const __nv_bfloat16 *src, *Wt;
        if (t < nt0) {
            tap = t / kt0; K0 = (t - tap * kt0) * BK;
            src = srcA; Wt = WtA; C = CA; H = HA; W = WA; sb = sAb; pad = padA;
        } else {
            int u = t - nt0;
            tap = u / kt1; K0 = (u - tap * kt1) * BK;
            src = srcB; Wt = WtB; C = CB; H = OH; W = OW; sb = sBb; pad = 1;
        }
        int y = s_py + tap / 3 - pad;
        int x = s_px + tap % 3 - pad;
        bool ok = s_valid && ((unsigned)y < (unsigned)H) && ((unsigned)x < (unsigned)W);
        const __nv_bfloat16* ap = ok
            ? src + (long)s_pb * sb + ((long)y * W + x) * C + K0 + ahalf * 16
            : src;
        int sz = ok ? 16 : 0;
        unsigned da = smem_u + buf * STAGE_B + arow * ROWB + ahalf * 32;
        cp16(da, ap, sz);
        cp16(da + 16, ap + 8, sz);
        // B: n-major row (arow), 64B per row
        const __nv_bfloat16* bp = Wt + ((long)tap * N + n0 + arow) * C + K0 + ahalf * 16;
        unsigned db = smem_u + buf * STAGE_B + A_TILE + arow * ROWB + ahalf * 32;
        cp16(db, bp, 16);
        cp16(db + 16, bp + 8, 16);
    };

    auto compute = [&](int buf) {
        unsigned Ab = smem_u + buf * STAGE_B;
        unsigned Bb = Ab + A_TILE;
#pragma unroll
        for (int ks = 0; ks < 2; ++ks) {
            unsigned a[4][4];
#pragma unroll
            for (int mi = 0; mi < 4; ++mi)
                ldsm_x4(a[mi][0], a[mi][1], a[mi][2], a[mi][3],
                        Ab + (unsigned)((wm + mi * 16 + a_lrow) * ROWB + a_koff + ks * 32));
            unsigned b[4][2];
#pragma unroll
            for (int np = 0; np < 2; ++np) {
                unsigned r0, r1, r2, r3;
                ldsm_x4(r0, r1, r2, r3,
                        Bb + (unsigned)((wn + np * 16 + b_lrow) * ROWB + b_koff + ks * 32));
                b[2 * np][0] = r0; b[2 * np][1] = r1;
                b[2 * np + 1][0] = r2; b[2 * np + 1][1] = r3;
            }
#pragma unroll
            for (int mi = 0; mi < 4; ++mi)
#pragma unroll
                for (int ni = 0; ni < 4; ++ni)
                    mma_bf16(acc[mi][ni], a[mi], b[ni]);
        }
    };

    // ---- 4-buffer pipelined main loop (one sync per tile) ----
    stage(0, 0);
    asm volatile("cp.async.commit_group;");
    stage(1, 1);
    asm volatile("cp.async.commit_group;");
    for (int t = 0; t < ntiles; ++t) {
        if (t + 2 < ntiles) {
            stage(t + 2, (t + 2) & 3);
            asm volatile("cp.async.commit_group;");
            asm volatile("cp.async.wait_group 2;");
        } else if (t + 1 < ntiles) {
            asm volatile("cp.async.wait_group 1;");
        } else {
            asm volatile("cp.async.wait_group 0;");
        }
        __syncthreads();
        compute(t & 3);
    }

    // ---- fp32 epilogue for the C=1 input conv (layer 1 only), interleaved W
    if (useX) {
        int epb[8], epy[8], epx[8];
        bool ev[8];
#pragma unroll
        for (int e = 0; e < 8; ++e) {
            int rr = m0 + wm + (e >> 1) * 16 + g + (e & 1) * 8;
            ev[e] = rr < M;
            int r2 = ev[e] ? rr : 0;
            epx[e] = r2 % OW; r2 /= OW;
            epy[e] = r2 % OH; epb[e] = r2 / OH;
        }
        for (int tap = 0; tap < 9; ++tap) {
            int dy = tap / 3, dx = tap % 3;   // VALID: pad 0
            float wv[4][2];
#pragma unroll
            for (int ni = 0; ni < 4; ++ni) {
                int col = n0 + wn + ni * 8 + 2 * tg;
                wv[ni][0] = WxI[tap * N + col];
                wv[ni][1] = WxI[tap * N + col + 1];
            }
#pragma unroll
            for (int e = 0; e < 8; ++e) if (ev[e]) {
                float xv = xsrc[(long)epb[e] * xsb + (long)(epy[e] + dy) * xW + (epx[e] + dx)];
#pragma unroll
                for (int ni = 0; ni < 4; ++ni) {
                    acc[e >> 1][ni][(e & 1) * 2 + 0] = fmaf(xv, wv[ni][0], acc[e >> 1][ni][(e & 1) * 2 + 0]);
                    acc[e >> 1][ni][(e & 1) * 2 + 1] = fmaf(xv, wv[ni][1], acc[e >> 1][ni][(e & 1) * 2 + 1]);
                }
            }
        }
    }

    // ---- fused LSTM epilogue ----
    __syncthreads();                       // all ring-buffer reads done
    float* S = (float*)smem;
#pragma unroll
    for (int mi = 0; mi < 4; ++mi) {
#pragma unroll
        for (int ni = 0; ni < 4; ++ni) {
            int c0 = wn + ni * 8 + 2 * tg;     // local interleaved col (even)
            int c1 = c0 + 1;
            int r0 = wm + mi * 16 + g;
            int r1 = r0 + 8;
            S[(c0 & 3) * SG + r0 * SROW + (c0 >> 2)] = acc[mi][ni][0];
            S[(c1 & 3) * SG + r0 * SROW + (c1 >> 2)] = acc[mi][ni][1];
            S[(c0 & 3) * SG + r1 * SROW + (c0 >> 2)] = acc[mi][ni][2];
            S[(c1 & 3) * SG + r1 * SROW + (c1 >> 2)] = acc[mi][ni][3];
        }
    }
    __syncthreads();

    {
        const int F = N >> 2;
        const int f0 = blockIdx.y * 32;
        const int fl = tid & 31;           // feature lane -> coalesced h/c
        const int rbase = (tid >> 5) * 16; // 8 warps x 16 rows
        const int fg = f0 + fl;
        const float bi = bias[fg];
        const float bfr = bias[F + fg];
        const float bc = bias[2 * F + fg];
        const float bo = bias[3 * F + fg];
#pragma unroll 4
        for (int rr = 0; rr < 16; ++rr) {
            int r = rbase + rr;
            int gm = m0 + r;
            if (gm < M) {
                float zi = S[0 * SG + r * SROW + fl] + bi;
                float zf = S[1 * SG + r * SROW + fl] + bfr;
                float zc = S[2 * SG + r * SROW + fl] + bc;
                float zo = S[3 * SG + r * SROW + fl] + bo;
                long ci = (long)gm * F + fg;
                float cn = sigmoidf_(zf) * c[ci] + sigmoidf_(zi) * tanhf(zc);
                float hn = sigmoidf_(zo) * tanhf(cn);
                c[ci] = cn;
                hb[ci] = __float2bfloat16(hn);
                if (hf) hf[ci] = hn;
            }
        }
    }
}

// ---------------------------------------------------------------------------
__global__ void dense_relu_kernel(const float* __restrict__ in,
                                  const float* __restrict__ W,
                                  const float* __restrict__ bias,
                                  float* __restrict__ out,
                                  int M, int K, int N, int do_relu)
{
    int idx = blockIdx.x * blockDim.x + threadIdx.x;
    if (idx >= M * N) return;
    int m = idx / N, n = idx % N;
    const float* ip = in + (long)m * K;
    float s = bias[n];
    for (int k = 0; k < K; ++k) s = fmaf(ip[k], W[k * N + n], s);
    if (do_relu) s = fmaxf(s, 0.f);
    out[idx] = s;
}

// ---------------------------------------------------------------------------
__global__ void final_fc_kernel(const float* __restrict__ dh,
                                const float* __restrict__ tin,
                                const float* __restrict__ locin,
                                const float* __restrict__ Wf1,
                                const float* __restrict__ bf1,
                                const float* __restrict__ Wf2,
                                const float* __restrict__ bf2,
                                float* __restrict__ out)
{
    int blk = blockIdx.x;              // = (b*30 + r)*28 + w
    int w = blk % 28;
    int r = (blk / 28) % 30;
    int b = blk / (28 * 30);

    __shared__ float v[64];
    __shared__ float red[64];
    int j = threadIdx.x;

    const float* src;
    if (r < 28)       src = dh    + (((long)(b * 28 + r)) * 28 + w) * 64;
    else if (r == 28) src = tin   + ((long)b * 28 + w) * 64;
    else              src = locin + ((long)b * 28 + w) * 64;
    v[j] = src[j];
    __syncthreads();

    float s = bf1[j];
#pragma unroll
    for (int k = 0; k < 64; ++k) s = fmaf(v[k], Wf1[k * 64 + j], s);
    s = fmaxf(s, 0.f) * Wf2[j];
    red[j] = s;
    __syncthreads();
    for (int off = 32; off > 0; off >>= 1) {
        if (j < off) red[j] += red[j + off];
        __syncthreads();
    }
    if (j == 0) out[blk] = red[0] + bf2[0];
}

// ---------------------------------------------------------------------------
extern "C" void kernel_launch(void* const* d_in, const int* in_sizes, int n_in,
                              void* d_out, int out_size)
{
    const float* x   = (const float*)d_in[0];
    const float* tt  = (const float*)d_in[1];
    const float* loc = (const float*)d_in[2];
    const float* Wx1 = (const float*)d_in[3];
    const float* Wh1 = (const float*)d_in[4];
    const float* b1  = (const float*)d_in[5];
    const float* Wx2 = (const float*)d_in[6];
    const float* Wh2 = (const float*)d_in[7];
    const float* b2  = (const float*)d_in[8];
    const float* Wd1 = (const float*)d_in[9];
    const float* bd1 = (const float*)d_in[10];
    const float* Wd2 = (const float*)d_in[11];
    const float* bd2 = (const float*)d_in[12];
    const float* Wf1 = (const float*)d_in[13];
    const float* bf1 = (const float*)d_in[14];
    const float* Wf2 = (const float*)d_in[15];
    const float* bf2 = (const float*)d_in[16];
    float* out = (float*)d_out;

    __nv_bfloat16 *h1b0, *h1b1, *h2b0, *h2b1, *Wt1, *Wt2x, *Wt2h;
    float *c1, *c2, *h2f, *scr256, *dh, *Wx1i;
    cudaGetSymbolAddress((void**)&h1b0, g_h1b);  h1b1 = h1b0 + H1N;
    cudaGetSymbolAddress((void**)&h2b0, g_h2b);  h2b1 = h2b0 + H2N;
    cudaGetSymbolAddress((void**)&c1, g_c1);
    cudaGetSymbolAddress((void**)&c2, g_c2);
    cudaGetSymbolAddress((void**)&h2f, g_h2f);
    cudaGetSymbolAddress((void**)&scr256, g_scr256);
    cudaGetSymbolAddress((void**)&dh, g_dh);
    cudaGetSymbolAddress((void**)&Wt1, g_Wt1);
    cudaGetSymbolAddress((void**)&Wt2x, g_Wt2x);
    cudaGetSymbolAddress((void**)&Wt2h, g_Wt2h);
    cudaGetSymbolAddress((void**)&Wx1i, g_Wx1i);

    cudaFuncSetAttribute(conv_lstm_kernel,
                         cudaFuncAttributeMaxDynamicSharedMemorySize, DSMEM_ALLOC);

    zero_state_kernel<<<1024, 256>>>();
    pack_wt_kernel<<<2048, 256>>>(Wh1, Wt1, 256, 1024, 9 * 1024 * 256);
    pack_wt_kernel<<<1024, 256>>>(Wx2, Wt2x, 256, 512, 9 * 512 * 256);
    pack_wt_kernel<<<512, 256>>>(Wh2, Wt2h, 128, 512, 9 * 512 * 128);
    interleave_kernel<<<36, 256>>>(Wx1, Wx1i, 1024, 9 * 1024);

    const int M1 = 8 * 30 * 30;   // 7200
    const int M2 = 8 * 28 * 28;   // 6272

    for (int ts = 0; ts < 10; ++ts) {
        int p = ts & 1;
        __nv_bfloat16* h1r = p ? h1b1 : h1b0;
        __nv_bfloat16* h1w = p ? h1b0 : h1b1;
        __nv_bfloat16* h2r = p ? h2b1 : h2b0;
        __nv_bfloat16* h2w = p ? h2b0 : h2b1;

        // L1: recurrent conv (h1r, SAME, C=256) + x-conv epilogue + LSTM -> h1w
        conv_lstm_kernel<<<dim3((M1 + BM - 1) / BM, 1024 / BN), 256, DSMEM_ALLOC>>>(
            h1r, 256, 30, 30, (long)30 * 30 * 256, 1, Wt1, /*kt0=*/0,
            h1r, 256, (long)30 * 30 * 256, Wt1, /*kt1=*/8,
            x + (long)ts * 32 * 32, 32, (long)10 * 32 * 32, Wx1i, /*useX=*/1,
            b1, h1w, nullptr, c1, 30, 30, 1024, M1);

        // L2: input conv (h1w, VALID, C=256) + recurrent conv (h2r, SAME, C=128) + LSTM -> h2w
        conv_lstm_kernel<<<dim3((M2 + BM - 1) / BM, 512 / BN), 256, DSMEM_ALLOC>>>(
            h1w, 256, 30, 30, (long)30 * 30 * 256, 0, Wt2x, /*kt0=*/8,
            h2r, 128, (long)28 * 28 * 128, Wt2h, /*kt1=*/4,
            x, 32, (long)10 * 32 * 32, Wx1i, /*useX=*/0,
            b2, h2w, h2f, c2, 28, 28, 512, M2);
    }

    dense_relu_kernel<<<(M2 * 256 + 255) / 256, 256>>>(h2f, Wd1, bd1, scr256, M2, 128, 256, 1);
    dense_relu_kernel<<<(M2 * 64 + 255) / 256, 256>>>(scr256, Wd2, bd2, dh, M2, 256, 64, 1);

    final_fc_kernel<<<8 * 30 * 28, 64>>>(dh, tt, loc, Wf1, bf1, Wf2, bf2, out);
}

// round 11
// speedup vs baseline: 1.4531x; 1.1472x over previous
#include <cuda_runtime.h>
#include <cuda_bf16.h>
#include <cstdint>
#include <math.h>

// ---------------------------------------------------------------------------
// Q6Model: 2-layer ConvLSTM (T=10) + dense head + concat + FC head
// Round 11 = R10 GEMM core (ldmatrix, BM=128/BN=128/BK=32, warp 64x32)
//  + B tiles pre-packed tile-contiguous in gmem, loaded with ONE
//    cp.async.bulk per tile (mbarrier complete_tx) -> halves LDGSTS issue.
//  + all setup fused into one launch. Fused LSTM epilogue, ping-pong h.
// ---------------------------------------------------------------------------

#define H1N (8*30*30*256)
#define H2N (8*28*28*128)

__device__ __nv_bfloat16 g_h1b[2][H1N];
__device__ float         g_c1[H1N];
__device__ __nv_bfloat16 g_h2b[2][H2N];
__device__ float         g_c2[H2N];
__device__ float         g_h2f[H2N];
__device__ float g_scr256[8*28*28*256];
__device__ float g_dh[8*28*28*64];
// tile-packed bf16 weights: [nb][tap][kt] tiles of (128 rows x 40 bf16),
// row = local gate-interleaved col n' (n' = 4*(n%F)+n/F), 32 k bf16 + 8 pad.
__device__ __nv_bfloat16 g_Wt1[8*9*8*5120];
__device__ __nv_bfloat16 g_Wt2x[4*9*8*5120];
__device__ __nv_bfloat16 g_Wt2h[4*9*4*5120];
// gate-interleaved fp32 x-conv weights
__device__ float g_Wx1i[9*1024];

// ---------------------------------------------------------------------------
// One-launch setup: zero state, pack 3 weight sets into tiles, interleave Wx1.
// ---------------------------------------------------------------------------
__device__ void pack_tiles_dev(const float* __restrict__ W, __nv_bfloat16* __restrict__ out,
                               int C, int N, int i, int stride)
{
    int ktiles = C / 32;
    int F = N >> 2;
    long total = (long)(N / 128) * 9 * ktiles * 5120;
    for (long e = i; e < total; e += stride) {
        int pos = (int)(e % 40);
        long r2 = e / 40;
        int row = (int)(r2 % 128);
        long tile = r2 / 128;
        int kt = (int)(tile % ktiles);
        int tap = (int)((tile / ktiles) % 9);
        int nb = (int)(tile / ((long)ktiles * 9));
        __nv_bfloat16 v = __float2bfloat16(0.f);
        if (pos < 32) {
            int np = nb * 128 + row;
            int g = np & 3, f = np >> 2;
            int n = g * F + f;
            v = __float2bfloat16(W[(long)(tap * C + kt * 32 + pos) * N + n]);
        }
        out[e] = v;
    }
}

__global__ void setup_kernel(const float* __restrict__ Wh1, const float* __restrict__ Wx2,
                             const float* __restrict__ Wh2, const float* __restrict__ Wx1)
{
    int i = blockIdx.x * blockDim.x + threadIdx.x;
    int stride = gridDim.x * blockDim.x;
    unsigned* h1u = (unsigned*)g_h1b;
    unsigned* h2u = (unsigned*)g_h2b;
    for (int k = i; k < H1N; k += stride) g_c1[k] = 0.f;
    for (int k = i; k < H1N; k += stride) h1u[k] = 0u;   // 2 bufs * H1N bf16 = H1N u32
    for (int k = i; k < H2N; k += stride) g_c2[k] = 0.f;
    for (int k = i; k < H2N; k += stride) h2u[k] = 0u;
    pack_tiles_dev(Wh1, g_Wt1, 256, 1024, i, stride);
    pack_tiles_dev(Wx2, g_Wt2x, 256, 512, i, stride);
    pack_tiles_dev(Wh2, g_Wt2h, 128, 512, i, stride);
    for (int idx = i; idx < 9 * 1024; idx += stride) {
        int n = idx % 1024;
        int t = idx / 1024;
        int np = 4 * (n % 256) + (n / 256);
        g_Wx1i[t * 1024 + np] = Wx1[idx];
    }
}

// ---------------------------------------------------------------------------
__device__ __forceinline__ void mma_bf16(float* d, const unsigned* a, const unsigned* b) {
    asm volatile(
        "mma.sync.aligned.m16n8k16.row.col.f32.bf16.bf16.f32 "
        "{%0,%1,%2,%3}, {%4,%5,%6,%7}, {%8,%9}, {%0,%1,%2,%3};\n"
        : "+f"(d[0]), "+f"(d[1]), "+f"(d[2]), "+f"(d[3])
        : "r"(a[0]), "r"(a[1]), "r"(a[2]), "r"(a[3]), "r"(b[0]), "r"(b[1]));
}

__device__ __forceinline__ void ldsm_x4(unsigned& r0, unsigned& r1, unsigned& r2, unsigned& r3,
                                        unsigned addr) {
    asm volatile("ldmatrix.sync.aligned.m8n8.x4.shared.b16 {%0,%1,%2,%3}, [%4];"
                 : "=r"(r0), "=r"(r1), "=r"(r2), "=r"(r3) : "r"(addr));
}

__device__ __forceinline__ void cp16(unsigned dst, const void* src, int sz) {
    asm volatile("cp.async.cg.shared.global [%0], [%1], 16, %2;"
                 :: "r"(dst), "l"(src), "r"(sz));
}

__device__ __forceinline__ void bulk_ld(unsigned dst, const void* src, unsigned bytes,
                                        unsigned mbar) {
    asm volatile(
        "cp.async.bulk.shared::cluster.global.mbarrier::complete_tx::bytes [%0], [%1], %2, [%3];"
        :: "r"(dst), "l"(src), "r"(bytes), "r"(mbar) : "memory");
}

__device__ __forceinline__ void mbar_init(unsigned mbar, unsigned cnt) {
    asm volatile("mbarrier.init.shared.b64 [%0], %1;" :: "r"(mbar), "r"(cnt) : "memory");
}

__device__ __forceinline__ void mbar_expect_tx(unsigned mbar, unsigned bytes) {
    asm volatile("mbarrier.arrive.expect_tx.shared.b64 _, [%0], %1;"
                 :: "r"(mbar), "r"(bytes) : "memory");
}

__device__ __forceinline__ void mbar_wait(unsigned mbar, unsigned parity) {
    unsigned done;
    asm volatile(
        "{\n\t.reg .pred p;\n\t"
        "mbarrier.try_wait.parity.shared.b64 p, [%1], %2;\n\t"
        "selp.b32 %0, 1, 0, p;\n\t}"
        : "=r"(done) : "r"(mbar), "r"(parity) : "memory");
    if (!done) {
        asm volatile(
            "{\n\t.reg .pred P1;\n\t"
            "WL_%=:\n\t"
            "mbarrier.try_wait.parity.shared.b64 P1, [%0], %1;\n\t"
            "@P1 bra.uni WD_%=;\n\t"
            "bra.uni WL_%=;\n\t"
            "WD_%=:\n\t}"
            :: "r"(mbar), "r"(parity) : "memory");
    }
}

__device__ __forceinline__ float sigmoidf_(float x) { return 1.f / (1.f + expf(-x)); }

// ---------------------------------------------------------------------------
// Fused conv-gates GEMM + LSTM update.
// BM=128, BN=128, BK=32 bf16. 256 threads = 8 warps (2M x 4N), warp 64x32.
// A tile: cp.async (2 ops/thread). B tile: ONE cp.async.bulk of 10240 B from
// the pre-packed tile image (rows 80 B = 64 data + 16 pad, conflict-free).
// 4-buffer ring: A via commit/wait_group, B via mbarrier parity.
// ---------------------------------------------------------------------------
#define BM 128
#define BN 128
#define BK 32
#define ROWB 80
#define A_TILE (BM*ROWB)                   // 10240
#define B_TILE (BN*ROWB)                   // 10240
#define STAGE_B (A_TILE + B_TILE)          // 20480
#define NBUF 4
#define SROW 33
#define SG (128*SROW)                      // 4224 words per gate plane
#define DSMEM_ALLOC (NBUF*STAGE_B)         // 81920 (> 4*SG*4 = 67584)

__global__ __launch_bounds__(256)
void conv_lstm_kernel(
    const __nv_bfloat16* __restrict__ srcA, int CA, int HA, int WA, long sAb, int padA,
    const __nv_bfloat16* __restrict__ WtA, int kt0,
    const __nv_bfloat16* __restrict__ srcB, int CB, long sBb,
    const __nv_bfloat16* __restrict__ WtB, int kt1,
    const float* __restrict__ xsrc, int xW, long xsb,
    const float* __restrict__ WxI, int useX,
    const float* __restrict__ bias,
    __nv_bfloat16* __restrict__ hb, float* __restrict__ hf,
    float* __restrict__ c,
    int OH, int OW, int N, int M)
{
    extern __shared__ char smem[];
    unsigned smem_u = (unsigned)__cvta_generic_to_shared(smem);
    __shared__ __align__(8) unsigned long long s_mbar[NBUF];

    const int tid = threadIdx.x;
    const int m0 = blockIdx.x * BM;
    const int n0 = blockIdx.y * BN;
    const int nb = blockIdx.y;
    const unsigned mb0 = (unsigned)__cvta_generic_to_shared(&s_mbar[0]);

    const int wid = tid >> 5, lane = tid & 31;
    const int wm = (wid >> 2) * 64;       // 2 warp rows (64 m each)
    const int wn = (wid & 3) * 32;        // 4 warp cols (32 n each)
    const int g = lane >> 2, tg = lane & 3;

    // ldmatrix lane-derived address components (validated R9/R10)
    const int a_lrow = lane & 15;
    const int a_koff = (lane & 16) ? 16 : 0;
    const int b_lrow = (lane & 7) + ((lane & 16) ? 8 : 0);
    const int b_koff = (lane & 8) ? 16 : 0;

    // A staging coords
    const int arow = tid >> 1;
    const int ahalf = tid & 1;

    if (tid == 0) {
#pragma unroll
        for (int q = 0; q < NBUF; ++q) mbar_init(mb0 + q * 8, 1);
    }
    __syncthreads();

    int s_pb = 0, s_py = 0, s_px = 0;
    bool s_valid;
    {
        int gm = m0 + arow;
        s_valid = gm < M;
        int r = s_valid ? gm : 0;
        s_px = r % OW; r /= OW;
        s_py = r % OH; s_pb = r / OH;
    }

    const int nt0 = 9 * kt0;
    const int ntiles = nt0 + 9 * kt1;

    float acc[4][4][4];
#pragma unroll
    for (int mi = 0; mi < 4; ++mi)
#pragma unroll
        for (int ni = 0; ni < 4; ++ni)
#pragma unroll
            for (int r = 0; r < 4; ++r) acc[mi][ni][r] = 0.f;

    auto stage = [&](int t, int buf) {
        int tap, ktl, K0, C, H, W, pad, ktn;
        long sb;
        const __nv_bfloat16 *src, *Wt;
        if (t < nt0) {
            tap = t / kt0; ktl = t - tap * kt0; ktn = kt0;
            src = srcA; Wt = WtA; C = CA; H = HA; W = WA; sb = sAb; pad = padA;
        } else {
            int u = t - nt0;
            tap = u / kt1; ktl = u - tap * kt1; ktn = kt1;
            src = srcB; Wt = WtB; C = CB; H = OH; W = OW; sb = sBb; pad = 1;
        }
        K0 = ktl * BK;
        // ---- A: cp.async, 2 ops/thread ----
        int y = s_py + tap / 3 - pad;
        int x = s_px + tap % 3 - pad;
        bool ok = s_valid && ((unsigned)y < (unsigned)H) && ((unsigned)x < (unsigned)W);
        const __nv_bfloat16* ap = ok
            ? src + (long)s_pb * sb + ((long)y * W + x) * C + K0 + ahalf * 16
            : src;
        int sz = ok ? 16 : 0;
        unsigned da = smem_u + buf * STAGE_B + arow * ROWB + ahalf * 32;
        cp16(da, ap, sz);
        cp16(da + 16, ap + 8, sz);
        // ---- B: ONE bulk copy of the pre-packed tile ----
        if (tid == 0) {
            const __nv_bfloat16* bt = Wt + (long)((nb * 9 + tap) * ktn + ktl) * 5120;
            unsigned mb = mb0 + buf * 8;
            mbar_expect_tx(mb, B_TILE);
            bulk_ld(smem_u + buf * STAGE_B + A_TILE, bt, B_TILE, mb);
        }
    };

    auto compute = [&](int buf) {
        unsigned Ab = smem_u + buf * STAGE_B;
        unsigned Bb = Ab + A_TILE;
#pragma unroll
        for (int ks = 0; ks < 2; ++ks) {
            unsigned a[4][4];
#pragma unroll
            for (int mi = 0; mi < 4; ++mi)
                ldsm_x4(a[mi][0], a[mi][1], a[mi][2], a[mi][3],
                        Ab + (unsigned)((wm + mi * 16 + a_lrow) * ROWB + a_koff + ks * 32));
            unsigned b[4][2];
#pragma unroll
            for (int np = 0; np < 2; ++np) {
                unsigned r0, r1, r2, r3;
                ldsm_x4(r0, r1, r2, r3,
                        Bb + (unsigned)((wn + np * 16 + b_lrow) * ROWB + b_koff + ks * 32));
                b[2 * np][0] = r0; b[2 * np][1] = r1;
                b[2 * np + 1][0] = r2; b[2 * np + 1][1] = r3;
            }
#pragma unroll
            for (int mi = 0; mi < 4; ++mi)
#pragma unroll
                for (int ni = 0; ni < 4; ++ni)
                    mma_bf16(acc[mi][ni], a[mi], b[ni]);
        }
    };

    // ---- 4-buffer pipelined main loop (one sync per tile) ----
    stage(0, 0);
    asm volatile("cp.async.commit_group;");
    stage(1, 1);
    asm volatile("cp.async.commit_group;");
    for (int t = 0; t < ntiles; ++t) {
        if (t + 2 < ntiles) {
            stage(t + 2, (t + 2) & 3);
            asm volatile("cp.async.commit_group;");
            asm volatile("cp.async.wait_group 2;");
        } else if (t + 1 < ntiles) {
            asm volatile("cp.async.wait_group 1;");
        } else {
            asm volatile("cp.async.wait_group 0;");
        }
        mbar_wait(mb0 + (t & 3) * 8, (t >> 2) & 1);
        __syncthreads();
        compute(t & 3);
    }

    // ---- fp32 epilogue for the C=1 input conv (layer 1 only), interleaved W
    if (useX) {
        int epb[8], epy[8], epx[8];
        bool ev[8];
#pragma unroll
        for (int e = 0; e < 8; ++e) {
            int rr = m0 + wm + (e >> 1) * 16 + g + (e & 1) * 8;
            ev[e] = rr < M;
            int r2 = ev[e] ? rr : 0;
            epx[e] = r2 % OW; r2 /= OW;
            epy[e] = r2 % OH; epb[e] = r2 / OH;
        }
        for (int tap = 0; tap < 9; ++tap) {
            int dy = tap / 3, dx = tap % 3;   // VALID: pad 0
            float wv[4][2];
#pragma unroll
            for (int ni = 0; ni < 4; ++ni) {
                int col = n0 + wn + ni * 8 + 2 * tg;
                wv[ni][0] = WxI[tap * N + col];
                wv[ni][1] = WxI[tap * N + col + 1];
            }
#pragma unroll
            for (int e = 0; e < 8; ++e) if (ev[e]) {
                float xv = xsrc[(long)epb[e] * xsb + (long)(epy[e] + dy) * xW + (epx[e] + dx)];
#pragma unroll
                for (int ni = 0; ni < 4; ++ni) {
                    acc[e >> 1][ni][(e & 1) * 2 + 0] = fmaf(xv, wv[ni][0], acc[e >> 1][ni][(e & 1) * 2 + 0]);
                    acc[e >> 1][ni][(e & 1) * 2 + 1] = fmaf(xv, wv[ni][1], acc[e >> 1][ni][(e & 1) * 2 + 1]);
                }
            }
        }
    }

    // ---- fused LSTM epilogue ----
    __syncthreads();                       // all ring-buffer reads done
    float* S = (float*)smem;
#pragma unroll
    for (int mi = 0; mi < 4; ++mi) {
#pragma unroll
        for (int ni = 0; ni < 4; ++ni) {
            int c0 = wn + ni * 8 + 2 * tg;     // local interleaved col (even)
            int c1 = c0 + 1;
            int r0 = wm + mi * 16 + g;
            int r1 = r0 + 8;
            S[(c0 & 3) * SG + r0 * SROW + (c0 >> 2)] = acc[mi][ni][0];
            S[(c1 & 3) * SG + r0 * SROW + (c1 >> 2)] = acc[mi][ni][1];
            S[(c0 & 3) * SG + r1 * SROW + (c0 >> 2)] = acc[mi][ni][2];
            S[(c1 & 3) * SG + r1 * SROW + (c1 >> 2)] = acc[mi][ni][3];
        }
    }
    __syncthreads();

    {
        const int F = N >> 2;
        const int f0 = blockIdx.y * 32;
        const int fl = tid & 31;           // feature lane -> coalesced h/c
        const int rbase = (tid >> 5) * 16; // 8 warps x 16 rows
        const int fg = f0 + fl;
        const float bi = bias[fg];
        const float bfr = bias[F + fg];
        const float bc = bias[2 * F + fg];
        const float bo = bias[3 * F + fg];
#pragma unroll 4
        for (int rr = 0; rr < 16; ++rr) {
            int r = rbase + rr;
            int gm = m0 + r;
            if (gm < M) {
                float zi = S[0 * SG + r * SROW + fl] + bi;
                float zf = S[1 * SG + r * SROW + fl] + bfr;
                float zc = S[2 * SG + r * SROW + fl] + bc;
                float zo = S[3 * SG + r * SROW + fl] + bo;
                long ci = (long)gm * F + fg;
                float cn = sigmoidf_(zf) * c[ci] + sigmoidf_(zi) * tanhf(zc);
                float hn = sigmoidf_(zo) * tanhf(cn);
                c[ci] = cn;
                hb[ci] = __float2bfloat16(hn);
                if (hf) hf[ci] = hn;
            }
        }
    }
}

// ---------------------------------------------------------------------------
__global__ void dense_relu_kernel(const float* __restrict__ in,
                                  const float* __restrict__ W,
                                  const float* __restrict__ bias,
                                  float* __restrict__ out,
                                  int M, int K, int N, int do_relu)
{
    int idx = blockIdx.x * blockDim.x + threadIdx.x;
    if (idx >= M * N) return;
    int m = idx / N, n = idx % N;
    const float* ip = in + (long)m * K;
    float s = bias[n];
    for (int k = 0; k < K; ++k) s = fmaf(ip[k], W[k * N + n], s);
    if (do_relu) s = fmaxf(s, 0.f);
    out[idx] = s;
}

// ---------------------------------------------------------------------------
__global__ void final_fc_kernel(const float* __restrict__ dh,
                                const float* __restrict__ tin,
                                const float* __restrict__ locin,
                                const float* __restrict__ Wf1,
                                const float* __restrict__ bf1,
                                const float* __restrict__ Wf2,
                                const float* __restrict__ bf2,
                                float* __restrict__ out)
{
    int blk = blockIdx.x;              // = (b*30 + r)*28 + w
    int w = blk % 28;
    int r = (blk / 28) % 30;
    int b = blk / (28 * 30);

    __shared__ float v[64];
    __shared__ float red[64];
    int j = threadIdx.x;

    const float* src;
    if (r < 28)       src = dh    + (((long)(b * 28 + r)) * 28 + w) * 64;
    else if (r == 28) src = tin   + ((long)b * 28 + w) * 64;
    else              src = locin + ((long)b * 28 + w) * 64;
    v[j] = src[j];
    __syncthreads();

    float s = bf1[j];
#pragma unroll
    for (int k = 0; k < 64; ++k) s = fmaf(v[k], Wf1[k * 64 + j], s);
    s = fmaxf(s, 0.f) * Wf2[j];
    red[j] = s;
    __syncthreads();
    for (int off = 32; off > 0; off >>= 1) {
        if (j < off) red[j] += red[j + off];
        __syncthreads();
    }
    if (j == 0) out[blk] = red[0] + bf2[0];
}

// ---------------------------------------------------------------------------
extern "C" void kernel_launch(void* const* d_in, const int* in_sizes, int n_in,
                              void* d_out, int out_size)
{
    const float* x   = (const float*)d_in[0];
    const float* tt  = (const float*)d_in[1];
    const float* loc = (const float*)d_in[2];
    const float* Wx1 = (const float*)d_in[3];
    const float* Wh1 = (const float*)d_in[4];
    const float* b1  = (const float*)d_in[5];
    const float* Wx2 = (const float*)d_in[6];
    const float* Wh2 = (const float*)d_in[7];
    const float* b2  = (const float*)d_in[8];
    const float* Wd1 = (const float*)d_in[9];
    const float* bd1 = (const float*)d_in[10];
    const float* Wd2 = (const float*)d_in[11];
    const float* bd2 = (const float*)d_in[12];
    const float* Wf1 = (const float*)d_in[13];
    const float* bf1 = (const float*)d_in[14];
    const float* Wf2 = (const float*)d_in[15];
    const float* bf2 = (const float*)d_in[16];
    float* out = (float*)d_out;

    __nv_bfloat16 *h1b0, *h1b1, *h2b0, *h2b1, *Wt1, *Wt2x, *Wt2h;
    float *c1, *c2, *h2f, *scr256, *dh, *Wx1i;
    cudaGetSymbolAddress((void**)&h1b0, g_h1b);  h1b1 = h1b0 + H1N;
    cudaGetSymbolAddress((void**)&h2b0, g_h2b);  h2b1 = h2b0 + H2N;
    cudaGetSymbolAddress((void**)&c1, g_c1);
    cudaGetSymbolAddress((void**)&c2, g_c2);
    cudaGetSymbolAddress((void**)&h2f, g_h2f);
    cudaGetSymbolAddress((void**)&scr256, g_scr256);
    cudaGetSymbolAddress((void**)&dh, g_dh);
    cudaGetSymbolAddress((void**)&Wt1, g_Wt1);
    cudaGetSymbolAddress((void**)&Wt2x, g_Wt2x);
    cudaGetSymbolAddress((void**)&Wt2h, g_Wt2h);
    cudaGetSymbolAddress((void**)&Wx1i, g_Wx1i);

    cudaFuncSetAttribute(conv_lstm_kernel,
                         cudaFuncAttributeMaxDynamicSharedMemorySize, DSMEM_ALLOC);

    setup_kernel<<<1024, 256>>>(Wh1, Wx2, Wh2, Wx1);

    const int M1 = 8 * 30 * 30;   // 7200
    const int M2 = 8 * 28 * 28;   // 6272

    for (int ts = 0; ts < 10; ++ts) {
        int p = ts & 1;
        __nv_bfloat16* h1r = p ? h1b1 : h1b0;
        __nv_bfloat16* h1w = p ? h1b0 : h1b1;
        __nv_bfloat16* h2r = p ? h2b1 : h2b0;
        __nv_bfloat16* h2w = p ? h2b0 : h2b1;

        // L1: recurrent conv (h1r, SAME, C=256) + x-conv epilogue + LSTM -> h1w
        conv_lstm_kernel<<<dim3((M1 + BM - 1) / BM, 1024 / BN), 256, DSMEM_ALLOC>>>(
            h1r, 256, 30, 30, (long)30 * 30 * 256, 1, Wt1, /*kt0=*/0,
            h1r, 256, (long)30 * 30 * 256, Wt1, /*kt1=*/8,
            x + (long)ts * 32 * 32, 32, (long)10 * 32 * 32, Wx1i, /*useX=*/1,
            b1, h1w, nullptr, c1, 30, 30, 1024, M1);

        // L2: input conv (h1w, VALID, C=256) + recurrent conv (h2r, SAME, C=128) + LSTM -> h2w
        conv_lstm_kernel<<<dim3((M2 + BM - 1) / BM, 512 / BN), 256, DSMEM_ALLOC>>>(
            h1w, 256, 30, 30, (long)30 * 30 * 256, 0, Wt2x, /*kt0=*/8,
            h2r, 128, (long)28 * 28 * 128, Wt2h, /*kt1=*/4,
            x, 32, (long)10 * 32 * 32, Wx1i, /*useX=*/0,
            b2, h2w, h2f, c2, 28, 28, 512, M2);
    }

    dense_relu_kernel<<<(M2 * 256 + 255) / 256, 256>>>(h2f, Wd1, bd1, scr256, M2, 128, 256, 1);
    dense_relu_kernel<<<(M2 * 64 + 255) / 256, 256>>>(scr256, Wd2, bd2, dh, M2, 256, 64, 1);

    final_fc_kernel<<<8 * 30 * 28, 64>>>(dh, tt, loc, Wf1, bf1, Wf2, bf2, out);
}

// round 12
// speedup vs baseline: 1.6979x; 1.1685x over previous
#include <cuda_runtime.h>
#include <cuda_bf16.h>
#include <cstdint>
#include <math.h>

// ---------------------------------------------------------------------------
// Q6Model: 2-layer ConvLSTM (T=10) + dense head + concat + FC head
// Round 12 = R11 + halo A-staging: image-row-aligned blocks (r = ly*32+lx),
// one 192-row halo per k-tile serves all 9 taps (9x fewer A LDGSTS);
// tap = constant ldmatrix offset. B tiles via cp.async.bulk ring (R11).
// Fused LSTM epilogue, ping-pong h. 28 launches.
// ---------------------------------------------------------------------------

#define H1N (8*30*30*256)
#define H2N (8*28*28*128)

__device__ __nv_bfloat16 g_h1b[2][H1N];
__device__ float         g_c1[H1N];
__device__ __nv_bfloat16 g_h2b[2][H2N];
__device__ float         g_c2[H2N];
__device__ float         g_h2f[H2N];
__device__ float g_scr256[8*28*28*256];
__device__ float g_dh[8*28*28*64];
// tile-packed bf16 weights: [nb][tap][kt] tiles of (128 rows x 40 bf16),
// row = local gate-interleaved col n' (n' = 4*(n%F)+n/F), 32 k bf16 + 8 pad.
__device__ __nv_bfloat16 g_Wt1[8*9*8*5120];
__device__ __nv_bfloat16 g_Wt2x[4*9*8*5120];
__device__ __nv_bfloat16 g_Wt2h[4*9*4*5120];
// gate-interleaved fp32 x-conv weights
__device__ float g_Wx1i[9*1024];

// ---------------------------------------------------------------------------
__device__ void pack_tiles_dev(const float* __restrict__ W, __nv_bfloat16* __restrict__ out,
                               int C, int N, int i, int stride)
{
    int ktiles = C / 32;
    int F = N >> 2;
    long total = (long)(N / 128) * 9 * ktiles * 5120;
    for (long e = i; e < total; e += stride) {
        int pos = (int)(e % 40);
        long r2 = e / 40;
        int row = (int)(r2 % 128);
        long tile = r2 / 128;
        int kt = (int)(tile % ktiles);
        int tap = (int)((tile / ktiles) % 9);
        int nb = (int)(tile / ((long)ktiles * 9));
        __nv_bfloat16 v = __float2bfloat16(0.f);
        if (pos < 32) {
            int np = nb * 128 + row;
            int g = np & 3, f = np >> 2;
            int n = g * F + f;
            v = __float2bfloat16(W[(long)(tap * C + kt * 32 + pos) * N + n]);
        }
        out[e] = v;
    }
}

__global__ void setup_kernel(const float* __restrict__ Wh1, const float* __restrict__ Wx2,
                             const float* __restrict__ Wh2, const float* __restrict__ Wx1)
{
    int i = blockIdx.x * blockDim.x + threadIdx.x;
    int stride = gridDim.x * blockDim.x;
    unsigned* h1u = (unsigned*)g_h1b;
    unsigned* h2u = (unsigned*)g_h2b;
    for (int k = i; k < H1N; k += stride) g_c1[k] = 0.f;
    for (int k = i; k < H1N; k += stride) h1u[k] = 0u;
    for (int k = i; k < H2N; k += stride) g_c2[k] = 0.f;
    for (int k = i; k < H2N; k += stride) h2u[k] = 0u;
    pack_tiles_dev(Wh1, g_Wt1, 256, 1024, i, stride);
    pack_tiles_dev(Wx2, g_Wt2x, 256, 512, i, stride);
    pack_tiles_dev(Wh2, g_Wt2h, 128, 512, i, stride);
    for (int idx = i; idx < 9 * 1024; idx += stride) {
        int n = idx % 1024;
        int t = idx / 1024;
        int np = 4 * (n % 256) + (n / 256);
        g_Wx1i[t * 1024 + np] = Wx1[idx];
    }
}

// ---------------------------------------------------------------------------
__device__ __forceinline__ void mma_bf16(float* d, const unsigned* a, const unsigned* b) {
    asm volatile(
        "mma.sync.aligned.m16n8k16.row.col.f32.bf16.bf16.f32 "
        "{%0,%1,%2,%3}, {%4,%5,%6,%7}, {%8,%9}, {%0,%1,%2,%3};\n"
        : "+f"(d[0]), "+f"(d[1]), "+f"(d[2]), "+f"(d[3])
        : "r"(a[0]), "r"(a[1]), "r"(a[2]), "r"(a[3]), "r"(b[0]), "r"(b[1]));
}

__device__ __forceinline__ void ldsm_x4(unsigned& r0, unsigned& r1, unsigned& r2, unsigned& r3,
                                        unsigned addr) {
    asm volatile("ldmatrix.sync.aligned.m8n8.x4.shared.b16 {%0,%1,%2,%3}, [%4];"
                 : "=r"(r0), "=r"(r1), "=r"(r2), "=r"(r3) : "r"(addr));
}

__device__ __forceinline__ void cp16(unsigned dst, const void* src, int sz) {
    asm volatile("cp.async.cg.shared.global [%0], [%1], 16, %2;"
                 :: "r"(dst), "l"(src), "r"(sz));
}

__device__ __forceinline__ void bulk_ld(unsigned dst, const void* src, unsigned bytes,
                                        unsigned mbar) {
    asm volatile(
        "cp.async.bulk.shared::cluster.global.mbarrier::complete_tx::bytes [%0], [%1], %2, [%3];"
        :: "r"(dst), "l"(src), "r"(bytes), "r"(mbar) : "memory");
}

__device__ __forceinline__ void mbar_init(unsigned mbar, unsigned cnt) {
    asm volatile("mbarrier.init.shared.b64 [%0], %1;" :: "r"(mbar), "r"(cnt) : "memory");
}

__device__ __forceinline__ void mbar_expect_tx(unsigned mbar, unsigned bytes) {
    asm volatile("mbarrier.arrive.expect_tx.shared.b64 _, [%0], %1;"
                 :: "r"(mbar), "r"(bytes) : "memory");
}

__device__ __forceinline__ void mbar_wait(unsigned mbar, unsigned parity) {
    unsigned done;
    asm volatile(
        "{\n\t.reg .pred p;\n\t"
        "mbarrier.try_wait.parity.shared.b64 p, [%1], %2;\n\t"
        "selp.b32 %0, 1, 0, p;\n\t}"
        : "=r"(done) : "r"(mbar), "r"(parity) : "memory");
    if (!done) {
        asm volatile(
            "{\n\t.reg .pred P1;\n\t"
            "WL_%=:\n\t"
            "mbarrier.try_wait.parity.shared.b64 P1, [%0], %1;\n\t"
            "@P1 bra.uni WD_%=;\n\t"
            "bra.uni WL_%=;\n\t"
            "WD_%=:\n\t}"
            :: "r"(mbar), "r"(parity) : "memory");
    }
}

__device__ __forceinline__ float sigmoidf_(float x) { return 1.f / (1.f + expf(-x)); }

// ---------------------------------------------------------------------------
// Fused conv-gates GEMM + LSTM update, halo A-staging.
// Block = (batch pb, 4 image rows y0..y0+3) x 128 gate-interleaved cols.
// M-row r = ly*32 + lx (lx >= OW slots masked). Halo: 6x32 = 192 rows x 64B
// of the k-slice, zero-padded; tap (dy,dx) = constant offset (dy*32+dx)*80.
// A: 768 LDGSTS per k-tile (vs 4608). B: one cp.async.bulk per (kt,tap).
// ---------------------------------------------------------------------------
#define HROWB 80
#define HALO_B (192*HROWB)                 // 15360
#define B_TILE 10240
#define BBUF_OFF (2*HALO_B)                // 30720
#define DSMEM_ALLOC (BBUF_OFF + 4*B_TILE)  // 71680
#define SROW 33
#define SG (128*SROW)                      // epilogue: 4*SG*4 = 67584 <= alloc

__global__ __launch_bounds__(256)
void conv_lstm_kernel(
    const __nv_bfloat16* __restrict__ srcA, int CA, int HA, int WA, long sAb, int padA,
    const __nv_bfloat16* __restrict__ WtA, int kt0,
    const __nv_bfloat16* __restrict__ srcB, int CB, int HB, int WB, long sBb, int padB,
    const __nv_bfloat16* __restrict__ WtB, int kt1,
    const float* __restrict__ xsrc, int xW, long xsb,
    const float* __restrict__ WxI, int useX,
    const float* __restrict__ bias,
    __nv_bfloat16* __restrict__ hb, float* __restrict__ hf,
    float* __restrict__ c,
    int OH, int OW, int YT, int N)
{
    extern __shared__ char smem[];
    unsigned smem_u = (unsigned)__cvta_generic_to_shared(smem);
    __shared__ __align__(8) unsigned long long s_mbar[4];

    const int tid = threadIdx.x;
    const int nb = blockIdx.y;
    const int n0 = nb * 128;
    const int y0 = (blockIdx.x % YT) * 4;
    const int pb = blockIdx.x / YT;
    const unsigned mb0 = (unsigned)__cvta_generic_to_shared(&s_mbar[0]);

    const int wid = tid >> 5, lane = tid & 31;
    const int wm = (wid >> 2) * 64;       // 2 warp rows (64 m each)
    const int wn = (wid & 3) * 32;        // 4 warp cols (32 n each)
    const int g = lane >> 2, tg = lane & 3;

    // ldmatrix lane-derived address components (validated R9-R11)
    const int a_lrow = lane & 15;
    const int a_koff = (lane & 16) ? 16 : 0;
    const int b_lrow = (lane & 7) + ((lane & 16) ? 8 : 0);
    const int b_koff = (lane & 8) ? 16 : 0;

    if (tid == 0) {
#pragma unroll
        for (int q = 0; q < 4; ++q) mbar_init(mb0 + q * 8, 1);
    }
    __syncthreads();

    const int ktotal = kt0 + kt1;
    const int total = 9 * ktotal;

    float acc[4][4][4];
#pragma unroll
    for (int mi = 0; mi < 4; ++mi)
#pragma unroll
        for (int ni = 0; ni < 4; ++ni)
#pragma unroll
            for (int r = 0; r < 4; ++r) acc[mi][ni][r] = 0.f;

    // stage the 192-row halo for global k-tile gk into buffer abuf
    auto stage_halo = [&](int gk, int abuf) {
        const __nv_bfloat16* src; int C, H, W, pad, K0; long sb;
        if (gk < kt0) { src = srcA; C = CA; H = HA; W = WA; sb = sAb; pad = padA; K0 = gk * 32; }
        else          { src = srcB; C = CB; H = HB; W = WB; sb = sBb; pad = padB; K0 = (gk - kt0) * 32; }
#pragma unroll
        for (int i = 0; i < 3; ++i) {
            int idx = tid + i * 256;         // 0..767
            int hr = idx >> 2, q = idx & 3;
            int h = hr >> 5, cx = hr & 31;
            int y = y0 - pad + h;
            int xx = cx - pad;
            bool ok = ((unsigned)y < (unsigned)H) && ((unsigned)xx < (unsigned)W);
            const __nv_bfloat16* sp = ok
                ? src + (long)pb * sb + ((long)y * W + xx) * C + K0 + q * 8
                : src;
            cp16(smem_u + abuf * HALO_B + hr * HROWB + q * 16, sp, ok ? 16 : 0);
        }
    };

    auto issueB = [&](int t) {
        if (tid == 0) {
            int gg = t / 9, tp = t - gg * 9;
            const __nv_bfloat16* Wt; int ktn, ktl;
            if (gg < kt0) { Wt = WtA; ktn = kt0; ktl = gg; }
            else          { Wt = WtB; ktn = kt1; ktl = gg - kt0; }
            const __nv_bfloat16* bt = Wt + (long)((nb * 9 + tp) * ktn + ktl) * 5120;
            unsigned mb = mb0 + (t & 3) * 8;
            mbar_expect_tx(mb, B_TILE);
            bulk_ld(smem_u + BBUF_OFF + (t & 3) * B_TILE, bt, B_TILE, mb);
        }
    };

    auto compute = [&](int abuf, int tshift, int bbuf) {
        unsigned Ab = smem_u + abuf * HALO_B + (unsigned)(tshift * HROWB);
        unsigned Bb = smem_u + BBUF_OFF + bbuf * B_TILE;
#pragma unroll
        for (int ks = 0; ks < 2; ++ks) {
            unsigned a[4][4];
#pragma unroll
            for (int mi = 0; mi < 4; ++mi)
                ldsm_x4(a[mi][0], a[mi][1], a[mi][2], a[mi][3],
                        Ab + (unsigned)((wm + mi * 16 + a_lrow) * HROWB + a_koff + ks * 32));
            unsigned b[4][2];
#pragma unroll
            for (int np = 0; np < 2; ++np) {
                unsigned r0, r1, r2, r3;
                ldsm_x4(r0, r1, r2, r3,
                        Bb + (unsigned)((wn + np * 16 + b_lrow) * HROWB + b_koff + ks * 32));
                b[2 * np][0] = r0; b[2 * np][1] = r1;
                b[2 * np + 1][0] = r2; b[2 * np + 1][1] = r3;
            }
#pragma unroll
            for (int mi = 0; mi < 4; ++mi)
#pragma unroll
                for (int ni = 0; ni < 4; ++ni)
                    mma_bf16(acc[mi][ni], a[mi], b[ni]);
        }
    };

    // ---- prologue ----
    issueB(0);
    issueB(1);
    stage_halo(0, 0);
    asm volatile("cp.async.commit_group;");

    // ---- main loop: k-tile outer, tap inner ----
    for (int gk = 0; gk < ktotal; ++gk) {
        asm volatile("cp.async.wait_group 0;");   // halo(gk) landed
        for (int tap = 0; tap < 9; ++tap) {
            __syncthreads();    // all warps done with B(t-2)'s buf and halo(gk-1)
            if (tap == 0 && gk + 1 < ktotal) {
                stage_halo(gk + 1, (gk + 1) & 1);
                asm volatile("cp.async.commit_group;");
            }
            int t = gk * 9 + tap;
            if (t + 2 < total) issueB(t + 2);
            mbar_wait(mb0 + (t & 3) * 8, (t >> 2) & 1);
            compute(gk & 1, (tap / 3) * 32 + (tap % 3), t & 3);
        }
    }

    // ---- fp32 epilogue for the C=1 input conv (layer 1 only), interleaved W
    if (useX) {
        int eply[8], eplx[8];
        bool ev[8];
#pragma unroll
        for (int e = 0; e < 8; ++e) {
            int rr = wm + (e >> 1) * 16 + g + (e & 1) * 8;   // local m-row 0..127
            int ly = rr >> 5, lx = rr & 31;
            ev[e] = (lx < OW) && (y0 + ly < OH);
            eply[e] = y0 + ly; eplx[e] = lx;
        }
        for (int tap = 0; tap < 9; ++tap) {
            int dy = tap / 3, dx = tap % 3;   // VALID: pad 0
            float wv[4][2];
#pragma unroll
            for (int ni = 0; ni < 4; ++ni) {
                int col = n0 + wn + ni * 8 + 2 * tg;
                wv[ni][0] = WxI[tap * N + col];
                wv[ni][1] = WxI[tap * N + col + 1];
            }
#pragma unroll
            for (int e = 0; e < 8; ++e) if (ev[e]) {
                float xv = xsrc[(long)pb * xsb + (long)(eply[e] + dy) * xW + (eplx[e] + dx)];
#pragma unroll
                for (int ni = 0; ni < 4; ++ni) {
                    acc[e >> 1][ni][(e & 1) * 2 + 0] = fmaf(xv, wv[ni][0], acc[e >> 1][ni][(e & 1) * 2 + 0]);
                    acc[e >> 1][ni][(e & 1) * 2 + 1] = fmaf(xv, wv[ni][1], acc[e >> 1][ni][(e & 1) * 2 + 1]);
                }
            }
        }
    }

    // ---- fused LSTM epilogue ----
    __syncthreads();                       // all halo/B reads done
    float* S = (float*)smem;
#pragma unroll
    for (int mi = 0; mi < 4; ++mi) {
#pragma unroll
        for (int ni = 0; ni < 4; ++ni) {
            int c0 = wn + ni * 8 + 2 * tg;     // local interleaved col (even)
            int c1 = c0 + 1;
            int r0 = wm + mi * 16 + g;
            int r1 = r0 + 8;
            S[(c0 & 3) * SG + r0 * SROW + (c0 >> 2)] = acc[mi][ni][0];
            S[(c1 & 3) * SG + r0 * SROW + (c1 >> 2)] = acc[mi][ni][1];
            S[(c0 & 3) * SG + r1 * SROW + (c0 >> 2)] = acc[mi][ni][2];
            S[(c1 & 3) * SG + r1 * SROW + (c1 >> 2)] = acc[mi][ni][3];
        }
    }
    __syncthreads();

    {
        const int F = N >> 2;
        const int f0 = nb * 32;
        const int fl = tid & 31;           // feature lane -> coalesced h/c
        const int rbase = (tid >> 5) * 16; // 8 warps x 16 rows
        const int fg = f0 + fl;
        const float bi = bias[fg];
        const float bfr = bias[F + fg];
        const float bc = bias[2 * F + fg];
        const float bo = bias[3 * F + fg];
#pragma unroll 4
        for (int rr = 0; rr < 16; ++rr) {
            int r = rbase + rr;
            int ly = r >> 5, lx = r & 31;
            if (lx < OW && y0 + ly < OH) {
                float zi = S[0 * SG + r * SROW + fl] + bi;
                float zf = S[1 * SG + r * SROW + fl] + bfr;
                float zc = S[2 * SG + r * SROW + fl] + bc;
                float zo = S[3 * SG + r * SROW + fl] + bo;
                long gm = (long)pb * OH * OW + (long)(y0 + ly) * OW + lx;
                long ci = gm * F + fg;
                float cn = sigmoidf_(zf) * c[ci] + sigmoidf_(zi) * tanhf(zc);
                float hn = sigmoidf_(zo) * tanhf(cn);
                c[ci] = cn;
                hb[ci] = __float2bfloat16(hn);
                if (hf) hf[ci] = hn;
            }
        }
    }
}

// ---------------------------------------------------------------------------
__global__ void dense_relu_kernel(const float* __restrict__ in,
                                  const float* __restrict__ W,
                                  const float* __restrict__ bias,
                                  float* __restrict__ out,
                                  int M, int K, int N, int do_relu)
{
    int idx = blockIdx.x * blockDim.x + threadIdx.x;
    if (idx >= M * N) return;
    int m = idx / N, n = idx % N;
    const float* ip = in + (long)m * K;
    float s = bias[n];
    for (int k = 0; k < K; ++k) s = fmaf(ip[k], W[k * N + n], s);
    if (do_relu) s = fmaxf(s, 0.f);
    out[idx] = s;
}

// ---------------------------------------------------------------------------
__global__ void final_fc_kernel(const float* __restrict__ dh,
                                const float* __restrict__ tin,
                                const float* __restrict__ locin,
                                const float* __restrict__ Wf1,
                                const float* __restrict__ bf1,
                                const float* __restrict__ Wf2,
                                const float* __restrict__ bf2,
                                float* __restrict__ out)
{
    int blk = blockIdx.x;              // = (b*30 + r)*28 + w
    int w = blk % 28;
    int r = (blk / 28) % 30;
    int b = blk / (28 * 30);

    __shared__ float v[64];
    __shared__ float red[64];
    int j = threadIdx.x;

    const float* src;
    if (r < 28)       src = dh    + (((long)(b * 28 + r)) * 28 + w) * 64;
    else if (r == 28) src = tin   + ((long)b * 28 + w) * 64;
    else              src = locin + ((long)b * 28 + w) * 64;
    v[j] = src[j];
    __syncthreads();

    float s = bf1[j];
#pragma unroll
    for (int k = 0; k < 64; ++k) s = fmaf(v[k], Wf1[k * 64 + j], s);
    s = fmaxf(s, 0.f) * Wf2[j];
    red[j] = s;
    __syncthreads();
    for (int off = 32; off > 0; off >>= 1) {
        if (j < off) red[j] += red[j + off];
        __syncthreads();
    }
    if (j == 0) out[blk] = red[0] + bf2[0];
}

// ---------------------------------------------------------------------------
extern "C" void kernel_launch(void* const* d_in, const int* in_sizes, int n_in,
                              void* d_out, int out_size)
{
    const float* x   = (const float*)d_in[0];
    const float* tt  = (const float*)d_in[1];
    const float* loc = (const float*)d_in[2];
    const float* Wx1 = (const float*)d_in[3];
    const float* Wh1 = (const float*)d_in[4];
    const float* b1  = (const float*)d_in[5];
    const float* Wx2 = (const float*)d_in[6];
    const float* Wh2 = (const float*)d_in[7];
    const float* b2  = (const float*)d_in[8];
    const float* Wd1 = (const float*)d_in[9];
    const float* bd1 = (const float*)d_in[10];
    const float* Wd2 = (const float*)d_in[11];
    const float* bd2 = (const float*)d_in[12];
    const float* Wf1 = (const float*)d_in[13];
    const float* bf1 = (const float*)d_in[14];
    const float* Wf2 = (const float*)d_in[15];
    const float* bf2 = (const float*)d_in[16];
    float* out = (float*)d_out;

    __nv_bfloat16 *h1b0, *h1b1, *h2b0, *h2b1, *Wt1, *Wt2x, *Wt2h;
    float *c1, *c2, *h2f, *scr256, *dh, *Wx1i;
    cudaGetSymbolAddress((void**)&h1b0, g_h1b);  h1b1 = h1b0 + H1N;
    cudaGetSymbolAddress((void**)&h2b0, g_h2b);  h2b1 = h2b0 + H2N;
    cudaGetSymbolAddress((void**)&c1, g_c1);
    cudaGetSymbolAddress((void**)&c2, g_c2);
    cudaGetSymbolAddress((void**)&h2f, g_h2f);
    cudaGetSymbolAddress((void**)&scr256, g_scr256);
    cudaGetSymbolAddress((void**)&dh, g_dh);
    cudaGetSymbolAddress((void**)&Wt1, g_Wt1);
    cudaGetSymbolAddress((void**)&Wt2x, g_Wt2x);
    cudaGetSymbolAddress((void**)&Wt2h, g_Wt2h);
    cudaGetSymbolAddress((void**)&Wx1i, g_Wx1i);

    cudaFuncSetAttribute(conv_lstm_kernel,
                         cudaFuncAttributeMaxDynamicSharedMemorySize, DSMEM_ALLOC);

    setup_kernel<<<1024, 256>>>(Wh1, Wx2, Wh2, Wx1);

    const int M2 = 8 * 28 * 28;   // 6272

    for (int ts = 0; ts < 10; ++ts) {
        int p = ts & 1;
        __nv_bfloat16* h1r = p ? h1b1 : h1b0;
        __nv_bfloat16* h1w = p ? h1b0 : h1b1;
        __nv_bfloat16* h2r = p ? h2b1 : h2b0;
        __nv_bfloat16* h2w = p ? h2b0 : h2b1;

        // L1: recurrent conv (h1r, 30x30 SAME, C=256) + x-conv epilogue + LSTM -> h1w
        conv_lstm_kernel<<<dim3(8 * 8, 8), 256, DSMEM_ALLOC>>>(
            h1r, 256, 30, 30, (long)30 * 30 * 256, 1, Wt1, /*kt0=*/0,
            h1r, 256, 30, 30, (long)30 * 30 * 256, 1, Wt1, /*kt1=*/8,
            x + (long)ts * 32 * 32, 32, (long)10 * 32 * 32, Wx1i, /*useX=*/1,
            b1, h1w, nullptr, c1, /*OH=*/30, /*OW=*/30, /*YT=*/8, /*N=*/1024);

        // L2: input conv (h1w, 30x30 VALID, C=256) + recurrent (h2r, 28x28 SAME, C=128) + LSTM -> h2w
        conv_lstm_kernel<<<dim3(8 * 7, 4), 256, DSMEM_ALLOC>>>(
            h1w, 256, 30, 30, (long)30 * 30 * 256, 0, Wt2x, /*kt0=*/8,
            h2r, 128, 28, 28, (long)28 * 28 * 128, 1, Wt2h, /*kt1=*/4,
            x, 32, (long)10 * 32 * 32, Wx1i, /*useX=*/0,
            b2, h2w, h2f, c2, /*OH=*/28, /*OW=*/28, /*YT=*/7, /*N=*/512);
    }

    dense_relu_kernel<<<(M2 * 256 + 255) / 256, 256>>>(h2f, Wd1, bd1, scr256, M2, 128, 256, 1);
    dense_relu_kernel<<<(M2 * 64 + 255) / 256, 256>>>(scr256, Wd2, bd2, dh, M2, 256, 64, 1);

    final_fc_kernel<<<8 * 30 * 28, 64>>>(dh, tt, loc, Wf1, bf1, Wf2, bf2, out);
}

// round 14
// speedup vs baseline: 1.8378x; 1.0824x over previous
#include <cuda_runtime.h>
#include <cuda_bf16.h>
#include <cstdint>
#include <math.h>

// ---------------------------------------------------------------------------
// Q6Model: 2-layer ConvLSTM (T=10) + dense head + concat + FC head
// Round 14 = R13 + the missing __syncthreads after the halo wait_group
// (cp.async.wait_group is per-thread; barrier makes all threads' halo copies
// visible before ldmatrix). Tap-row B groups (3 taps / bulk copy, 2-ring,
// tid0 mbar wait), halo A-staging, fused LSTM epilogue, ping-pong h.
// ---------------------------------------------------------------------------

#define H1N (8*30*30*256)
#define H2N (8*28*28*128)

__device__ __nv_bfloat16 g_h1b[2][H1N];
__device__ float         g_c1[H1N];
__device__ __nv_bfloat16 g_h2b[2][H2N];
__device__ float         g_c2[H2N];
__device__ float         g_h2f[H2N];
__device__ float g_scr256[8*28*28*256];
__device__ float g_dh[8*28*28*64];
// tile-packed bf16 weights: [nb][kt][tap] tiles of (128 rows x 40 bf16),
// row = local gate-interleaved col n' (n' = 4*(n%F)+n/F), 32 k bf16 + 8 pad.
__device__ __nv_bfloat16 g_Wt1[8*8*9*5120];
__device__ __nv_bfloat16 g_Wt2x[4*8*9*5120];
__device__ __nv_bfloat16 g_Wt2h[4*4*9*5120];
// gate-interleaved fp32 x-conv weights
__device__ float g_Wx1i[9*1024];

// ---------------------------------------------------------------------------
__device__ void pack_tiles_dev(const float* __restrict__ W, __nv_bfloat16* __restrict__ out,
                               int C, int N, int i, int stride)
{
    int ktiles = C / 32;
    int F = N >> 2;
    long total = (long)(N / 128) * 9 * ktiles * 5120;
    for (long e = i; e < total; e += stride) {
        int pos = (int)(e % 40);
        long r2 = e / 40;
        int row = (int)(r2 % 128);
        long tile = r2 / 128;
        // layout: [nb][kt][tap]
        int tap = (int)(tile % 9);
        int kt = (int)((tile / 9) % ktiles);
        int nb = (int)(tile / ((long)ktiles * 9));
        __nv_bfloat16 v = __float2bfloat16(0.f);
        if (pos < 32) {
            int np = nb * 128 + row;
            int g = np & 3, f = np >> 2;
            int n = g * F + f;
            v = __float2bfloat16(W[(long)(tap * C + kt * 32 + pos) * N + n]);
        }
        out[e] = v;
    }
}

__global__ void setup_kernel(const float* __restrict__ Wh1, const float* __restrict__ Wx2,
                             const float* __restrict__ Wh2, const float* __restrict__ Wx1)
{
    int i = blockIdx.x * blockDim.x + threadIdx.x;
    int stride = gridDim.x * blockDim.x;
    unsigned* h1u = (unsigned*)g_h1b;
    unsigned* h2u = (unsigned*)g_h2b;
    for (int k = i; k < H1N; k += stride) g_c1[k] = 0.f;
    for (int k = i; k < H1N; k += stride) h1u[k] = 0u;
    for (int k = i; k < H2N; k += stride) g_c2[k] = 0.f;
    for (int k = i; k < H2N; k += stride) h2u[k] = 0u;
    pack_tiles_dev(Wh1, g_Wt1, 256, 1024, i, stride);
    pack_tiles_dev(Wx2, g_Wt2x, 256, 512, i, stride);
    pack_tiles_dev(Wh2, g_Wt2h, 128, 512, i, stride);
    for (int idx = i; idx < 9 * 1024; idx += stride) {
        int n = idx % 1024;
        int t = idx / 1024;
        int np = 4 * (n % 256) + (n / 256);
        g_Wx1i[t * 1024 + np] = Wx1[idx];
    }
}

// ---------------------------------------------------------------------------
__device__ __forceinline__ void mma_bf16(float* d, const unsigned* a, const unsigned* b) {
    asm volatile(
        "mma.sync.aligned.m16n8k16.row.col.f32.bf16.bf16.f32 "
        "{%0,%1,%2,%3}, {%4,%5,%6,%7}, {%8,%9}, {%0,%1,%2,%3};\n"
        : "+f"(d[0]), "+f"(d[1]), "+f"(d[2]), "+f"(d[3])
        : "r"(a[0]), "r"(a[1]), "r"(a[2]), "r"(a[3]), "r"(b[0]), "r"(b[1]));
}

__device__ __forceinline__ void ldsm_x4(unsigned& r0, unsigned& r1, unsigned& r2, unsigned& r3,
                                        unsigned addr) {
    asm volatile("ldmatrix.sync.aligned.m8n8.x4.shared.b16 {%0,%1,%2,%3}, [%4];"
                 : "=r"(r0), "=r"(r1), "=r"(r2), "=r"(r3) : "r"(addr));
}

__device__ __forceinline__ void cp16(unsigned dst, const void* src, int sz) {
    asm volatile("cp.async.cg.shared.global [%0], [%1], 16, %2;"
                 :: "r"(dst), "l"(src), "r"(sz));
}

__device__ __forceinline__ void bulk_ld(unsigned dst, const void* src, unsigned bytes,
                                        unsigned mbar) {
    asm volatile(
        "cp.async.bulk.shared::cluster.global.mbarrier::complete_tx::bytes [%0], [%1], %2, [%3];"
        :: "r"(dst), "l"(src), "r"(bytes), "r"(mbar) : "memory");
}

__device__ __forceinline__ void mbar_init(unsigned mbar, unsigned cnt) {
    asm volatile("mbarrier.init.shared.b64 [%0], %1;" :: "r"(mbar), "r"(cnt) : "memory");
}

__device__ __forceinline__ void mbar_expect_tx(unsigned mbar, unsigned bytes) {
    asm volatile("mbarrier.arrive.expect_tx.shared.b64 _, [%0], %1;"
                 :: "r"(mbar), "r"(bytes) : "memory");
}

__device__ __forceinline__ void mbar_wait(unsigned mbar, unsigned parity) {
    unsigned done;
    asm volatile(
        "{\n\t.reg .pred p;\n\t"
        "mbarrier.try_wait.parity.shared.b64 p, [%1], %2;\n\t"
        "selp.b32 %0, 1, 0, p;\n\t}"
        : "=r"(done) : "r"(mbar), "r"(parity) : "memory");
    if (!done) {
        asm volatile(
            "{\n\t.reg .pred P1;\n\t"
            "WL_%=:\n\t"
            "mbarrier.try_wait.parity.shared.b64 P1, [%0], %1;\n\t"
            "@P1 bra.uni WD_%=;\n\t"
            "bra.uni WL_%=;\n\t"
            "WD_%=:\n\t}"
            :: "r"(mbar), "r"(parity) : "memory");
    }
}

__device__ __forceinline__ float sigmoidf_(float x) { return 1.f / (1.f + expf(-x)); }

// ---------------------------------------------------------------------------
// Fused conv-gates GEMM + LSTM update, halo A-staging + tap-row B groups.
// Block = (batch pb, 4 image rows y0..y0+3) x 128 gate-interleaved cols.
// Halo: 192 rows x 64B k-slice (double-buffered). B: 3-tap group (30720B)
// per cp.async.bulk, 2-group ring, tid0 mbar wait + barrier per group.
// ---------------------------------------------------------------------------
#define HROWB 80
#define HALO_B (192*HROWB)                 // 15360
#define B_TILE 10240
#define B_GROUP (3*B_TILE)                 // 30720
#define BBUF_OFF (2*HALO_B)                // 30720
#define DSMEM_ALLOC (BBUF_OFF + 2*B_GROUP) // 92160
#define SROW 33
#define SG (128*SROW)                      // epilogue: 4*SG*4 = 67584 <= alloc

__global__ __launch_bounds__(256)
void conv_lstm_kernel(
    const __nv_bfloat16* __restrict__ srcA, int CA, int HA, int WA, long sAb, int padA,
    const __nv_bfloat16* __restrict__ WtA, int kt0,
    const __nv_bfloat16* __restrict__ srcB, int CB, int HB, int WB, long sBb, int padB,
    const __nv_bfloat16* __restrict__ WtB, int kt1,
    const float* __restrict__ xsrc, int xW, long xsb,
    const float* __restrict__ WxI, int useX,
    const float* __restrict__ bias,
    __nv_bfloat16* __restrict__ hb, float* __restrict__ hf,
    float* __restrict__ c,
    int OH, int OW, int YT, int N)
{
    extern __shared__ char smem[];
    unsigned smem_u = (unsigned)__cvta_generic_to_shared(smem);
    __shared__ __align__(8) unsigned long long s_mbar[2];

    const int tid = threadIdx.x;
    const int nb = blockIdx.y;
    const int n0 = nb * 128;
    const int y0 = (blockIdx.x % YT) * 4;
    const int pb = blockIdx.x / YT;
    const unsigned mb0 = (unsigned)__cvta_generic_to_shared(&s_mbar[0]);

    const int wid = tid >> 5, lane = tid & 31;
    const int wm = (wid >> 2) * 64;       // 2 warp rows (64 m each)
    const int wn = (wid & 3) * 32;        // 4 warp cols (32 n each)
    const int g = lane >> 2, tg = lane & 3;

    // ldmatrix lane-derived address components (validated R9-R12)
    const int a_lrow = lane & 15;
    const int a_koff = (lane & 16) ? 16 : 0;
    const int b_lrow = (lane & 7) + ((lane & 16) ? 8 : 0);
    const int b_koff = (lane & 8) ? 16 : 0;

    if (tid == 0) {
        mbar_init(mb0, 1);
        mbar_init(mb0 + 8, 1);
    }
    __syncthreads();

    const int ktotal = kt0 + kt1;
    const int G = 3 * ktotal;             // tap-row groups

    float acc[4][4][4];
#pragma unroll
    for (int mi = 0; mi < 4; ++mi)
#pragma unroll
        for (int ni = 0; ni < 4; ++ni)
#pragma unroll
            for (int r = 0; r < 4; ++r) acc[mi][ni][r] = 0.f;

    // stage the 192-row halo for global k-tile gk into buffer abuf
    auto stage_halo = [&](int gk, int abuf) {
        const __nv_bfloat16* src; int C, H, W, pad, K0; long sb;
        if (gk < kt0) { src = srcA; C = CA; H = HA; W = WA; sb = sAb; pad = padA; K0 = gk * 32; }
        else          { src = srcB; C = CB; H = HB; W = WB; sb = sBb; pad = padB; K0 = (gk - kt0) * 32; }
#pragma unroll
        for (int i = 0; i < 3; ++i) {
            int idx = tid + i * 256;         // 0..767
            int hr = idx >> 2, q = idx & 3;
            int h = hr >> 5, cx = hr & 31;
            int y = y0 - pad + h;
            int xx = cx - pad;
            bool ok = ((unsigned)y < (unsigned)H) && ((unsigned)xx < (unsigned)W);
            const __nv_bfloat16* sp = ok
                ? src + (long)pb * sb + ((long)y * W + xx) * C + K0 + q * 8
                : src;
            cp16(smem_u + abuf * HALO_B + hr * HROWB + q * 16, sp, ok ? 16 : 0);
        }
    };

    // issue one 3-tap B group (group index gq)
    auto issueB = [&](int gq) {
        if (tid == 0) {
            int gg = gq / 3, tr = gq - gg * 3;
            const __nv_bfloat16* Wt; int ktn, ktl;
            if (gg < kt0) { Wt = WtA; ktn = kt0; ktl = gg; }
            else          { Wt = WtB; ktn = kt1; ktl = gg - kt0; }
            const __nv_bfloat16* bt = Wt + (long)((nb * ktn + ktl) * 9 + tr * 3) * 5120;
            unsigned mb = mb0 + (gq & 1) * 8;
            mbar_expect_tx(mb, B_GROUP);
            bulk_ld(smem_u + BBUF_OFF + (gq & 1) * B_GROUP, bt, B_GROUP, mb);
        }
    };

    // compute one tap: halo buffer abuf, tap shift, B tile base address
    auto compute = [&](int abuf, int tshift, unsigned Bb) {
        unsigned Ab = smem_u + abuf * HALO_B + (unsigned)(tshift * HROWB);
#pragma unroll
        for (int ks = 0; ks < 2; ++ks) {
            unsigned a[4][4];
#pragma unroll
            for (int mi = 0; mi < 4; ++mi)
                ldsm_x4(a[mi][0], a[mi][1], a[mi][2], a[mi][3],
                        Ab + (unsigned)((wm + mi * 16 + a_lrow) * HROWB + a_koff + ks * 32));
            unsigned b[4][2];
#pragma unroll
            for (int np = 0; np < 2; ++np) {
                unsigned r0, r1, r2, r3;
                ldsm_x4(r0, r1, r2, r3,
                        Bb + (unsigned)((wn + np * 16 + b_lrow) * HROWB + b_koff + ks * 32));
                b[2 * np][0] = r0; b[2 * np][1] = r1;
                b[2 * np + 1][0] = r2; b[2 * np + 1][1] = r3;
            }
#pragma unroll
            for (int mi = 0; mi < 4; ++mi)
#pragma unroll
                for (int ni = 0; ni < 4; ++ni)
                    mma_bf16(acc[mi][ni], a[mi], b[ni]);
        }
    };

    // ---- prologue ----
    issueB(0);
    issueB(1);
    stage_halo(0, 0);
    asm volatile("cp.async.commit_group;");

    // ---- main loop over 3-tap groups ----
    for (int gq = 0; gq < G; ++gq) {
        int gk = gq / 3, tr = gq - gk * 3;
        if (tid == 0) mbar_wait(mb0 + (gq & 1) * 8, (gq >> 1) & 1);
        __syncthreads();          // B(gq) visible; compute(gq-1) done everywhere
        if (gq >= 1 && gq + 1 < G) issueB(gq + 1);
        if (tr == 0) {
            if (gk + 1 < ktotal) {
                stage_halo(gk + 1, (gk + 1) & 1);
                asm volatile("cp.async.commit_group;");
                asm volatile("cp.async.wait_group 1;");   // OWN halo(gk) copies landed
            } else {
                asm volatile("cp.async.wait_group 0;");
            }
            __syncthreads();      // ALL threads' halo(gk) copies landed & visible
        }
        unsigned Bg = smem_u + BBUF_OFF + (gq & 1) * B_GROUP;
#pragma unroll
        for (int i = 0; i < 3; ++i) {
            compute(gk & 1, tr * 32 + i, Bg + i * B_TILE);
        }
    }

    // ---- fp32 epilogue for the C=1 input conv (layer 1 only), interleaved W
    if (useX) {
        int eply[8], eplx[8];
        bool ev[8];
#pragma unroll
        for (int e = 0; e < 8; ++e) {
            int rr = wm + (e >> 1) * 16 + g + (e & 1) * 8;   // local m-row 0..127
            int ly = rr >> 5, lx = rr & 31;
            ev[e] = (lx < OW) && (y0 + ly < OH);
            eply[e] = y0 + ly; eplx[e] = lx;
        }
        for (int tap = 0; tap < 9; ++tap) {
            int dy = tap / 3, dx = tap % 3;   // VALID: pad 0
            float wv[4][2];
#pragma unroll
            for (int ni = 0; ni < 4; ++ni) {
                int col = n0 + wn + ni * 8 + 2 * tg;
                wv[ni][0] = WxI[tap * N + col];
                wv[ni][1] = WxI[tap * N + col + 1];
            }
#pragma unroll
            for (int e = 0; e < 8; ++e) if (ev[e]) {
                float xv = xsrc[(long)pb * xsb + (long)(eply[e] + dy) * xW + (eplx[e] + dx)];
#pragma unroll
                for (int ni = 0; ni < 4; ++ni) {
                    acc[e >> 1][ni][(e & 1) * 2 + 0] = fmaf(xv, wv[ni][0], acc[e >> 1][ni][(e & 1) * 2 + 0]);
                    acc[e >> 1][ni][(e & 1) * 2 + 1] = fmaf(xv, wv[ni][1], acc[e >> 1][ni][(e & 1) * 2 + 1]);
                }
            }
        }
    }

    // ---- fused LSTM epilogue ----
    __syncthreads();                       // all halo/B reads done
    float* S = (float*)smem;
#pragma unroll
    for (int mi = 0; mi < 4; ++mi) {
#pragma unroll
        for (int ni = 0; ni < 4; ++ni) {
            int c0 = wn + ni * 8 + 2 * tg;     // local interleaved col (even)
            int c1 = c0 + 1;
            int r0 = wm + mi * 16 + g;
            int r1 = r0 + 8;
            S[(c0 & 3) * SG + r0 * SROW + (c0 >> 2)] = acc[mi][ni][0];
            S[(c1 & 3) * SG + r0 * SROW + (c1 >> 2)] = acc[mi][ni][1];
            S[(c0 & 3) * SG + r1 * SROW + (c0 >> 2)] = acc[mi][ni][2];
            S[(c1 & 3) * SG + r1 * SROW + (c1 >> 2)] = acc[mi][ni][3];
        }
    }
    __syncthreads();

    {
        const int F = N >> 2;
        const int f0 = nb * 32;
        const int fl = tid & 31;           // feature lane -> coalesced h/c
        const int rbase = (tid >> 5) * 16; // 8 warps x 16 rows
        const int fg = f0 + fl;
        const float bi = bias[fg];
        const float bfr = bias[F + fg];
        const float bc = bias[2 * F + fg];
        const float bo = bias[3 * F + fg];
#pragma unroll 4
        for (int rr = 0; rr < 16; ++rr) {
            int r = rbase + rr;
            int ly = r >> 5, lx = r & 31;
            if (lx < OW && y0 + ly < OH) {
                float zi = S[0 * SG + r * SROW + fl] + bi;
                float zf = S[1 * SG + r * SROW + fl] + bfr;
                float zc = S[2 * SG + r * SROW + fl] + bc;
                float zo = S[3 * SG + r * SROW + fl] + bo;
                long gm = (long)pb * OH * OW + (long)(y0 + ly) * OW + lx;
                long ci = gm * F + fg;
                float cn = sigmoidf_(zf) * c[ci] + sigmoidf_(zi) * tanhf(zc);
                float hn = sigmoidf_(zo) * tanhf(cn);
                c[ci] = cn;
                hb[ci] = __float2bfloat16(hn);
                if (hf) hf[ci] = hn;
            }
        }
    }
}

// ---------------------------------------------------------------------------
__global__ void dense_relu_kernel(const float* __restrict__ in,
                                  const float* __restrict__ W,
                                  const float* __restrict__ bias,
                                  float* __restrict__ out,
                                  int M, int K, int N, int do_relu)
{
    int idx = blockIdx.x * blockDim.x + threadIdx.x;
    if (idx >= M * N) return;
    int m = idx / N, n = idx % N;
    const float* ip = in + (long)m * K;
    float s = bias[n];
    for (int k = 0; k < K; ++k) s = fmaf(ip[k], W[k * N + n], s);
    if (do_relu) s = fmaxf(s, 0.f);
    out[idx] = s;
}

// ---------------------------------------------------------------------------
__global__ void final_fc_kernel(const float* __restrict__ dh,
                                const float* __restrict__ tin,
                                const float* __restrict__ locin,
                                const float* __restrict__ Wf1,
                                const float* __restrict__ bf1,
                                const float* __restrict__ Wf2,
                                const float* __restrict__ bf2,
                                float* __restrict__ out)
{
    int blk = blockIdx.x;              // = (b*30 + r)*28 + w
    int w = blk % 28;
    int r = (blk / 28) % 30;
    int b = blk / (28 * 30);

    __shared__ float v[64];
    __shared__ float red[64];
    int j = threadIdx.x;

    const float* src;
    if (r < 28)       src = dh    + (((long)(b * 28 + r)) * 28 + w) * 64;
    else if (r == 28) src = tin   + ((long)b * 28 + w) * 64;
    else              src = locin + ((long)b * 28 + w) * 64;
    v[j] = src[j];
    __syncthreads();

    float s = bf1[j];
#pragma unroll
    for (int k = 0; k < 64; ++k) s = fmaf(v[k], Wf1[k * 64 + j], s);
    s = fmaxf(s, 0.f) * Wf2[j];
    red[j] = s;
    __syncthreads();
    for (int off = 32; off > 0; off >>= 1) {
        if (j < off) red[j] += red[j + off];
        __syncthreads();
    }
    if (j == 0) out[blk] = red[0] + bf2[0];
}

// ---------------------------------------------------------------------------
extern "C" void kernel_launch(void* const* d_in, const int* in_sizes, int n_in,
                              void* d_out, int out_size)
{
    const float* x   = (const float*)d_in[0];
    const float* tt  = (const float*)d_in[1];
    const float* loc = (const float*)d_in[2];
    const float* Wx1 = (const float*)d_in[3];
    const float* Wh1 = (const float*)d_in[4];
    const float* b1  = (const float*)d_in[5];
    const float* Wx2 = (const float*)d_in[6];
    const float* Wh2 = (const float*)d_in[7];
    const float* b2  = (const float*)d_in[8];
    const float* Wd1 = (const float*)d_in[9];
    const float* bd1 = (const float*)d_in[10];
    const float* Wd2 = (const float*)d_in[11];
    const float* bd2 = (const float*)d_in[12];
    const float* Wf1 = (const float*)d_in[13];
    const float* bf1 = (const float*)d_in[14];
    const float* Wf2 = (const float*)d_in[15];
    const float* bf2 = (const float*)d_in[16];
    float* out = (float*)d_out;

    __nv_bfloat16 *h1b0, *h1b1, *h2b0, *h2b1, *Wt1, *Wt2x, *Wt2h;
    float *c1, *c2, *h2f, *scr256, *dh, *Wx1i;
    cudaGetSymbolAddress((void**)&h1b0, g_h1b);  h1b1 = h1b0 + H1N;
    cudaGetSymbolAddress((void**)&h2b0, g_h2b);  h2b1 = h2b0 + H2N;
    cudaGetSymbolAddress((void**)&c1, g_c1);
    cudaGetSymbolAddress((void**)&c2, g_c2);
    cudaGetSymbolAddress((void**)&h2f, g_h2f);
    cudaGetSymbolAddress((void**)&scr256, g_scr256);
    cudaGetSymbolAddress((void**)&dh, g_dh);
    cudaGetSymbolAddress((void**)&Wt1, g_Wt1);
    cudaGetSymbolAddress((void**)&Wt2x, g_Wt2x);
    cudaGetSymbolAddress((void**)&Wt2h, g_Wt2h);
    cudaGetSymbolAddress((void**)&Wx1i, g_Wx1i);

    cudaFuncSetAttribute(conv_lstm_kernel,
                         cudaFuncAttributeMaxDynamicSharedMemorySize, DSMEM_ALLOC);

    setup_kernel<<<1024, 256>>>(Wh1, Wx2, Wh2, Wx1);

    const int M2 = 8 * 28 * 28;   // 6272

    for (int ts = 0; ts < 10; ++ts) {
        int p = ts & 1;
        __nv_bfloat16* h1r = p ? h1b1 : h1b0;
        __nv_bfloat16* h1w = p ? h1b0 : h1b1;
        __nv_bfloat16* h2r = p ? h2b1 : h2b0;
        __nv_bfloat16* h2w = p ? h2b0 : h2b1;

        // L1: recurrent conv (h1r, 30x30 SAME, C=256) + x-conv epilogue + LSTM -> h1w
        conv_lstm_kernel<<<dim3(8 * 8, 8), 256, DSMEM_ALLOC>>>(
            h1r, 256, 30, 30, (long)30 * 30 * 256, 1, Wt1, /*kt0=*/0,
            h1r, 256, 30, 30, (long)30 * 30 * 256, 1, Wt1, /*kt1=*/8,
            x + (long)ts * 32 * 32, 32, (long)10 * 32 * 32, Wx1i, /*useX=*/1,
            b1, h1w, nullptr, c1, /*OH=*/30, /*OW=*/30, /*YT=*/8, /*N=*/1024);

        // L2: input conv (h1w, 30x30 VALID, C=256) + recurrent (h2r, 28x28 SAME, C=128) + LSTM -> h2w
        conv_lstm_kernel<<<dim3(8 * 7, 4), 256, DSMEM_ALLOC>>>(
            h1w, 256, 30, 30, (long)30 * 30 * 256, 0, Wt2x, /*kt0=*/8,
            h2r, 128, 28, 28, (long)28 * 28 * 128, 1, Wt2h, /*kt1=*/4,
            x, 32, (long)10 * 32 * 32, Wx1i, /*useX=*/0,
            b2, h2w, h2f, c2, /*OH=*/28, /*OW=*/28, /*YT=*/7, /*N=*/512);
    }

    dense_relu_kernel<<<(M2 * 256 + 255) / 256, 256>>>(h2f, Wd1, bd1, scr256, M2, 128, 256, 1);
    dense_relu_kernel<<<(M2 * 64 + 255) / 256, 256>>>(scr256, Wd2, bd2, dh, M2, 256, 64, 1);

    final_fc_kernel<<<8 * 30 * 28, 64>>>(dh, tt, loc, Wf1, bf1, Wf2, bf2, out);
}

// round 16
// speedup vs baseline: 2.1447x; 1.1670x over previous
#include <cuda_runtime.h>
#include <cuda_bf16.h>
#include <cstdint>
#include <math.h>

// ---------------------------------------------------------------------------
// Q6Model: 2-layer ConvLSTM (T=10) + dense head + concat + FC head
// Round 16 = R14 conv body (verified) + cross-layer launch fusion:
// launch k runs L1(k) and L2(k-1) together (independent work, deps via
// launch boundaries). 20 conv launches -> 11. Everything else unchanged.
// ---------------------------------------------------------------------------

#define H1N (8*30*30*256)
#define H2N (8*28*28*128)

__device__ __nv_bfloat16 g_h1b[2][H1N];
__device__ float         g_c1[H1N];
__device__ __nv_bfloat16 g_h2b[2][H2N];
__device__ float         g_c2[H2N];
__device__ float         g_h2f[H2N];
__device__ float g_scr256[8*28*28*256];
__device__ float g_dh[8*28*28*64];
// tile-packed bf16 weights: [nb][kt][tap] tiles of (128 rows x 40 bf16)
__device__ __nv_bfloat16 g_Wt1[8*8*9*5120];
__device__ __nv_bfloat16 g_Wt2x[4*8*9*5120];
__device__ __nv_bfloat16 g_Wt2h[4*4*9*5120];
__device__ float g_Wx1i[9*1024];

// ---------------------------------------------------------------------------
__device__ void pack_tiles_dev(const float* __restrict__ W, __nv_bfloat16* __restrict__ out,
                               int C, int N, int i, int stride)
{
    int ktiles = C / 32;
    int F = N >> 2;
    long total = (long)(N / 128) * 9 * ktiles * 5120;
    for (long e = i; e < total; e += stride) {
        int pos = (int)(e % 40);
        long r2 = e / 40;
        int row = (int)(r2 % 128);
        long tile = r2 / 128;
        int tap = (int)(tile % 9);
        int kt = (int)((tile / 9) % ktiles);
        int nb = (int)(tile / ((long)ktiles * 9));
        __nv_bfloat16 v = __float2bfloat16(0.f);
        if (pos < 32) {
            int np = nb * 128 + row;
            int g = np & 3, f = np >> 2;
            int n = g * F + f;
            v = __float2bfloat16(W[(long)(tap * C + kt * 32 + pos) * N + n]);
        }
        out[e] = v;
    }
}

__global__ void setup_kernel(const float* __restrict__ Wh1, const float* __restrict__ Wx2,
                             const float* __restrict__ Wh2, const float* __restrict__ Wx1)
{
    int i = blockIdx.x * blockDim.x + threadIdx.x;
    int stride = gridDim.x * blockDim.x;
    unsigned* h1u = (unsigned*)g_h1b;
    unsigned* h2u = (unsigned*)g_h2b;
    for (int k = i; k < H1N; k += stride) g_c1[k] = 0.f;
    for (int k = i; k < H1N; k += stride) h1u[k] = 0u;
    for (int k = i; k < H2N; k += stride) g_c2[k] = 0.f;
    for (int k = i; k < H2N; k += stride) h2u[k] = 0u;
    pack_tiles_dev(Wh1, g_Wt1, 256, 1024, i, stride);
    pack_tiles_dev(Wx2, g_Wt2x, 256, 512, i, stride);
    pack_tiles_dev(Wh2, g_Wt2h, 128, 512, i, stride);
    for (int idx = i; idx < 9 * 1024; idx += stride) {
        int n = idx % 1024;
        int t = idx / 1024;
        int np = 4 * (n % 256) + (n / 256);
        g_Wx1i[t * 1024 + np] = Wx1[idx];
    }
}

// ---------------------------------------------------------------------------
__device__ __forceinline__ void mma_bf16(float* d, const unsigned* a, const unsigned* b) {
    asm volatile(
        "mma.sync.aligned.m16n8k16.row.col.f32.bf16.bf16.f32 "
        "{%0,%1,%2,%3}, {%4,%5,%6,%7}, {%8,%9}, {%0,%1,%2,%3};\n"
        : "+f"(d[0]), "+f"(d[1]), "+f"(d[2]), "+f"(d[3])
        : "r"(a[0]), "r"(a[1]), "r"(a[2]), "r"(a[3]), "r"(b[0]), "r"(b[1]));
}

__device__ __forceinline__ void ldsm_x4(unsigned& r0, unsigned& r1, unsigned& r2, unsigned& r3,
                                        unsigned addr) {
    asm volatile("ldmatrix.sync.aligned.m8n8.x4.shared.b16 {%0,%1,%2,%3}, [%4];"
                 : "=r"(r0), "=r"(r1), "=r"(r2), "=r"(r3) : "r"(addr));
}

__device__ __forceinline__ void cp16(unsigned dst, const void* src, int sz) {
    asm volatile("cp.async.cg.shared.global [%0], [%1], 16, %2;"
                 :: "r"(dst), "l"(src), "r"(sz));
}

__device__ __forceinline__ void bulk_ld(unsigned dst, const void* src, unsigned bytes,
                                        unsigned mbar) {
    asm volatile(
        "cp.async.bulk.shared::cluster.global.mbarrier::complete_tx::bytes [%0], [%1], %2, [%3];"
        :: "r"(dst), "l"(src), "r"(bytes), "r"(mbar) : "memory");
}

__device__ __forceinline__ void mbar_init(unsigned mbar, unsigned cnt) {
    asm volatile("mbarrier.init.shared.b64 [%0], %1;" :: "r"(mbar), "r"(cnt) : "memory");
}

__device__ __forceinline__ void mbar_expect_tx(unsigned mbar, unsigned bytes) {
    asm volatile("mbarrier.arrive.expect_tx.shared.b64 _, [%0], %1;"
                 :: "r"(mbar), "r"(bytes) : "memory");
}

__device__ __forceinline__ void mbar_wait(unsigned mbar, unsigned parity) {
    unsigned done;
    asm volatile(
        "{\n\t.reg .pred p;\n\t"
        "mbarrier.try_wait.parity.shared.b64 p, [%1], %2;\n\t"
        "selp.b32 %0, 1, 0, p;\n\t}"
        : "=r"(done) : "r"(mbar), "r"(parity) : "memory");
    if (!done) {
        asm volatile(
            "{\n\t.reg .pred P1;\n\t"
            "WL_%=:\n\t"
            "mbarrier.try_wait.parity.shared.b64 P1, [%0], %1;\n\t"
            "@P1 bra.uni WD_%=;\n\t"
            "bra.uni WL_%=;\n\t"
            "WD_%=:\n\t}"
            :: "r"(mbar), "r"(parity) : "memory");
    }
}

__device__ __forceinline__ float sigmoidf_(float x) { return 1.f / (1.f + expf(-x)); }

// ---------------------------------------------------------------------------
// R14 conv body, verbatim, parameterized on (bx, nb) instead of blockIdx.
// ---------------------------------------------------------------------------
#define HROWB 80
#define HALO_B (192*HROWB)                 // 15360
#define B_TILE 10240
#define B_GROUP (3*B_TILE)                 // 30720
#define BBUF_OFF (2*HALO_B)                // 30720
#define DSMEM_ALLOC (BBUF_OFF + 2*B_GROUP) // 92160
#define SROW 33
#define SG (128*SROW)                      // epilogue: 4*SG*4 = 67584 <= alloc

__device__ void conv_body(
    const __nv_bfloat16* __restrict__ srcA, int CA, int HA, int WA, long sAb, int padA,
    const __nv_bfloat16* __restrict__ WtA, int kt0,
    const __nv_bfloat16* __restrict__ srcB, int CB, int HB, int WB, long sBb, int padB,
    const __nv_bfloat16* __restrict__ WtB, int kt1,
    const float* __restrict__ xsrc, int xW, long xsb,
    const float* __restrict__ WxI, int useX,
    const float* __restrict__ bias,
    __nv_bfloat16* __restrict__ hb, float* __restrict__ hf,
    float* __restrict__ c,
    int OH, int OW, int YT, int N, int bx, int nb)
{
    extern __shared__ char smem[];
    unsigned smem_u = (unsigned)__cvta_generic_to_shared(smem);
    __shared__ __align__(8) unsigned long long s_mbar[2];

    const int tid = threadIdx.x;
    const int n0 = nb * 128;
    const int y0 = (bx % YT) * 4;
    const int pb = bx / YT;
    const unsigned mb0 = (unsigned)__cvta_generic_to_shared(&s_mbar[0]);

    const int wid = tid >> 5, lane = tid & 31;
    const int wm = (wid >> 2) * 64;
    const int wn = (wid & 3) * 32;
    const int g = lane >> 2, tg = lane & 3;

    const int a_lrow = lane & 15;
    const int a_koff = (lane & 16) ? 16 : 0;
    const int b_lrow = (lane & 7) + ((lane & 16) ? 8 : 0);
    const int b_koff = (lane & 8) ? 16 : 0;

    if (tid == 0) {
        mbar_init(mb0, 1);
        mbar_init(mb0 + 8, 1);
    }
    __syncthreads();

    const int ktotal = kt0 + kt1;
    const int G = 3 * ktotal;

    float acc[4][4][4];
#pragma unroll
    for (int mi = 0; mi < 4; ++mi)
#pragma unroll
        for (int ni = 0; ni < 4; ++ni)
#pragma unroll
            for (int r = 0; r < 4; ++r) acc[mi][ni][r] = 0.f;

    auto stage_halo = [&](int gk, int abuf) {
        const __nv_bfloat16* src; int C, H, W, pad, K0; long sb;
        if (gk < kt0) { src = srcA; C = CA; H = HA; W = WA; sb = sAb; pad = padA; K0 = gk * 32; }
        else          { src = srcB; C = CB; H = HB; W = WB; sb = sBb; pad = padB; K0 = (gk - kt0) * 32; }
#pragma unroll
        for (int i = 0; i < 3; ++i) {
            int idx = tid + i * 256;
            int hr = idx >> 2, q = idx & 3;
            int h = hr >> 5, cx = hr & 31;
            int y = y0 - pad + h;
            int xx = cx - pad;
            bool ok = ((unsigned)y < (unsigned)H) && ((unsigned)xx < (unsigned)W);
            const __nv_bfloat16* sp = ok
                ? src + (long)pb * sb + ((long)y * W + xx) * C + K0 + q * 8
                : src;
            cp16(smem_u + abuf * HALO_B + hr * HROWB + q * 16, sp, ok ? 16 : 0);
        }
    };

    auto issueB = [&](int gq) {
        if (tid == 0) {
            int gg = gq / 3, tr = gq - gg * 3;
            const __nv_bfloat16* Wt; int ktn, ktl;
            if (gg < kt0) { Wt = WtA; ktn = kt0; ktl = gg; }
            else          { Wt = WtB; ktn = kt1; ktl = gg - kt0; }
            const __nv_bfloat16* bt = Wt + (long)((nb * ktn + ktl) * 9 + tr * 3) * 5120;
            unsigned mb = mb0 + (gq & 1) * 8;
            mbar_expect_tx(mb, B_GROUP);
            bulk_ld(smem_u + BBUF_OFF + (gq & 1) * B_GROUP, bt, B_GROUP, mb);
        }
    };

    auto compute = [&](int abuf, int tshift, unsigned Bb) {
        unsigned Ab = smem_u + abuf * HALO_B + (unsigned)(tshift * HROWB);
#pragma unroll
        for (int ks = 0; ks < 2; ++ks) {
            unsigned a[4][4];
#pragma unroll
            for (int mi = 0; mi < 4; ++mi)
                ldsm_x4(a[mi][0], a[mi][1], a[mi][2], a[mi][3],
                        Ab + (unsigned)((wm + mi * 16 + a_lrow) * HROWB + a_koff + ks * 32));
            unsigned b[4][2];
#pragma unroll
            for (int np = 0; np < 2; ++np) {
                unsigned r0, r1, r2, r3;
                ldsm_x4(r0, r1, r2, r3,
                        Bb + (unsigned)((wn + np * 16 + b_lrow) * HROWB + b_koff + ks * 32));
                b[2 * np][0] = r0; b[2 * np][1] = r1;
                b[2 * np + 1][0] = r2; b[2 * np + 1][1] = r3;
            }
#pragma unroll
            for (int mi = 0; mi < 4; ++mi)
#pragma unroll
                for (int ni = 0; ni < 4; ++ni)
                    mma_bf16(acc[mi][ni], a[mi], b[ni]);
        }
    };

    // ---- prologue ----
    issueB(0);
    issueB(1);
    stage_halo(0, 0);
    asm volatile("cp.async.commit_group;");

    // ---- main loop over 3-tap groups ----
    for (int gq = 0; gq < G; ++gq) {
        int gk = gq / 3, tr = gq - gk * 3;
        if (tid == 0) mbar_wait(mb0 + (gq & 1) * 8, (gq >> 1) & 1);
        __syncthreads();          // B(gq) visible; compute(gq-1) done everywhere
        if (gq >= 1 && gq + 1 < G) issueB(gq + 1);
        if (tr == 0) {
            if (gk + 1 < ktotal) {
                stage_halo(gk + 1, (gk + 1) & 1);
                asm volatile("cp.async.commit_group;");
                asm volatile("cp.async.wait_group 1;");   // OWN halo(gk) copies landed
            } else {
                asm volatile("cp.async.wait_group 0;");
            }
            __syncthreads();      // ALL threads' halo(gk) copies landed & visible
        }
        unsigned Bg = smem_u + BBUF_OFF + (gq & 1) * B_GROUP;
#pragma unroll
        for (int i = 0; i < 3; ++i) {
            compute(gk & 1, tr * 32 + i, Bg + i * B_TILE);
        }
    }

    // ---- fp32 epilogue for the C=1 input conv (layer 1 only), interleaved W
    if (useX) {
        int eply[8], eplx[8];
        bool ev[8];
#pragma unroll
        for (int e = 0; e < 8; ++e) {
            int rr = wm + (e >> 1) * 16 + g + (e & 1) * 8;
            int ly = rr >> 5, lx = rr & 31;
            ev[e] = (lx < OW) && (y0 + ly < OH);
            eply[e] = y0 + ly; eplx[e] = lx;
        }
        for (int tap = 0; tap < 9; ++tap) {
            int dy = tap / 3, dx = tap % 3;
            float wv[4][2];
#pragma unroll
            for (int ni = 0; ni < 4; ++ni) {
                int col = n0 + wn + ni * 8 + 2 * tg;
                wv[ni][0] = WxI[tap * N + col];
                wv[ni][1] = WxI[tap * N + col + 1];
            }
#pragma unroll
            for (int e = 0; e < 8; ++e) if (ev[e]) {
                float xv = xsrc[(long)pb * xsb + (long)(eply[e] + dy) * xW + (eplx[e] + dx)];
#pragma unroll
                for (int ni = 0; ni < 4; ++ni) {
                    acc[e >> 1][ni][(e & 1) * 2 + 0] = fmaf(xv, wv[ni][0], acc[e >> 1][ni][(e & 1) * 2 + 0]);
                    acc[e >> 1][ni][(e & 1) * 2 + 1] = fmaf(xv, wv[ni][1], acc[e >> 1][ni][(e & 1) * 2 + 1]);
                }
            }
        }
    }

    // ---- fused LSTM epilogue ----
    __syncthreads();
    float* S = (float*)smem;
#pragma unroll
    for (int mi = 0; mi < 4; ++mi) {
#pragma unroll
        for (int ni = 0; ni < 4; ++ni) {
            int c0 = wn + ni * 8 + 2 * tg;
            int c1 = c0 + 1;
            int r0 = wm + mi * 16 + g;
            int r1 = r0 + 8;
            S[(c0 & 3) * SG + r0 * SROW + (c0 >> 2)] = acc[mi][ni][0];
            S[(c1 & 3) * SG + r0 * SROW + (c1 >> 2)] = acc[mi][ni][1];
            S[(c0 & 3) * SG + r1 * SROW + (c0 >> 2)] = acc[mi][ni][2];
            S[(c1 & 3) * SG + r1 * SROW + (c1 >> 2)] = acc[mi][ni][3];
        }
    }
    __syncthreads();

    {
        const int F = N >> 2;
        const int f0 = nb * 32;
        const int fl = tid & 31;
        const int rbase = (tid >> 5) * 16;
        const int fg = f0 + fl;
        const float bi = bias[fg];
        const float bfr = bias[F + fg];
        const float bc = bias[2 * F + fg];
        const float bo = bias[3 * F + fg];
#pragma unroll 4
        for (int rr = 0; rr < 16; ++rr) {
            int r = rbase + rr;
            int ly = r >> 5, lx = r & 31;
            if (lx < OW && y0 + ly < OH) {
                float zi = S[0 * SG + r * SROW + fl] + bi;
                float zf = S[1 * SG + r * SROW + fl] + bfr;
                float zc = S[2 * SG + r * SROW + fl] + bc;
                float zo = S[3 * SG + r * SROW + fl] + bo;
                long gm = (long)pb * OH * OW + (long)(y0 + ly) * OW + lx;
                long ci = gm * F + fg;
                float cn = sigmoidf_(zf) * c[ci] + sigmoidf_(zi) * tanhf(zc);
                float hn = sigmoidf_(zo) * tanhf(cn);
                c[ci] = cn;
                hb[ci] = __float2bfloat16(hn);
                if (hf) hf[ci] = hn;
            }
        }
    }
}

// ---------------------------------------------------------------------------
// Fused step: blocks [0,512) run L1(tsA); blocks [512,736) run L2(tsB).
// tsA or tsB may be -1 (role absent). Dependencies via launch boundaries.
// ---------------------------------------------------------------------------
__global__ __launch_bounds__(256)
void fused_step_kernel(int tsA, int tsB,
                       const float* __restrict__ x,
                       const float* __restrict__ b1,
                       const float* __restrict__ b2)
{
    const int boundary = (tsA >= 0) ? 512 : 0;
    const int bid = blockIdx.x;
    if (bid < boundary) {
        // L1 at tsA: recurrent conv (h1 prev, 30x30 SAME, C=256) + x epilogue
        int bx = bid & 63, nb = bid >> 6;
        int p = tsA & 1;
        const __nv_bfloat16* h1r = p ? g_h1b[1] : g_h1b[0];
        __nv_bfloat16* h1w = p ? g_h1b[0] : g_h1b[1];
        conv_body(h1r, 256, 30, 30, (long)30 * 30 * 256, 1, g_Wt1, /*kt0=*/0,
                  h1r, 256, 30, 30, (long)30 * 30 * 256, 1, g_Wt1, /*kt1=*/8,
                  x + (long)tsA * 32 * 32, 32, (long)10 * 32 * 32, g_Wx1i, /*useX=*/1,
                  b1, h1w, nullptr, g_c1,
                  /*OH=*/30, /*OW=*/30, /*YT=*/8, /*N=*/1024, bx, nb);
    } else {
        // L2 at tsB: input conv (h1(tsB), 30x30 VALID) + recurrent (h2 prev, SAME)
        int lb = bid - boundary;
        int bx = lb % 56, nb = lb / 56;
        int p = tsB & 1;
        const __nv_bfloat16* h1w = p ? g_h1b[0] : g_h1b[1];   // h1 output at tsB
        const __nv_bfloat16* h2r = p ? g_h2b[1] : g_h2b[0];
        __nv_bfloat16* h2w = p ? g_h2b[0] : g_h2b[1];
        conv_body(h1w, 256, 30, 30, (long)30 * 30 * 256, 0, g_Wt2x, /*kt0=*/8,
                  h2r, 128, 28, 28, (long)28 * 28 * 128, 1, g_Wt2h, /*kt1=*/4,
                  x, 32, (long)10 * 32 * 32, g_Wx1i, /*useX=*/0,
                  b2, h2w, g_h2f, g_c2,
                  /*OH=*/28, /*OW=*/28, /*YT=*/7, /*N=*/512, bx, nb);
    }
}

// ---------------------------------------------------------------------------
__global__ void dense_relu_kernel(const float* __restrict__ in,
                                  const float* __restrict__ W,
                                  const float* __restrict__ bias,
                                  float* __restrict__ out,
                                  int M, int K, int N, int do_relu)
{
    int idx = blockIdx.x * blockDim.x + threadIdx.x;
    if (idx >= M * N) return;
    int m = idx / N, n = idx % N;
    const float* ip = in + (long)m * K;
    float s = bias[n];
    for (int k = 0; k < K; ++k) s = fmaf(ip[k], W[k * N + n], s);
    if (do_relu) s = fmaxf(s, 0.f);
    out[idx] = s;
}

// ---------------------------------------------------------------------------
__global__ void final_fc_kernel(const float* __restrict__ dh,
                                const float* __restrict__ tin,
                                const float* __restrict__ locin,
                                const float* __restrict__ Wf1,
                                const float* __restrict__ bf1,
                                const float* __restrict__ Wf2,
                                const float* __restrict__ bf2,
                                float* __restrict__ out)
{
    int blk = blockIdx.x;              // = (b*30 + r)*28 + w
    int w = blk % 28;
    int r = (blk / 28) % 30;
    int b = blk / (28 * 30);

    __shared__ float v[64];
    __shared__ float red[64];
    int j = threadIdx.x;

    const float* src;
    if (r < 28)       src = dh    + (((long)(b * 28 + r)) * 28 + w) * 64;
    else if (r == 28) src = tin   + ((long)b * 28 + w) * 64;
    else              src = locin + ((long)b * 28 + w) * 64;
    v[j] = src[j];
    __syncthreads();

    float s = bf1[j];
#pragma unroll
    for (int k = 0; k < 64; ++k) s = fmaf(v[k], Wf1[k * 64 + j], s);
    s = fmaxf(s, 0.f) * Wf2[j];
    red[j] = s;
    __syncthreads();
    for (int off = 32; off > 0; off >>= 1) {
        if (j < off) red[j] += red[j + off];
        __syncthreads();
    }
    if (j == 0) out[blk] = red[0] + bf2[0];
}

// ---------------------------------------------------------------------------
extern "C" void kernel_launch(void* const* d_in, const int* in_sizes, int n_in,
                              void* d_out, int out_size)
{
    const float* x   = (const float*)d_in[0];
    const float* tt  = (const float*)d_in[1];
    const float* loc = (const float*)d_in[2];
    const float* Wx1 = (const float*)d_in[3];
    const float* Wh1 = (const float*)d_in[4];
    const float* b1  = (const float*)d_in[5];
    const float* Wx2 = (const float*)d_in[6];
    const float* Wh2 = (const float*)d_in[7];
    const float* b2  = (const float*)d_in[8];
    const float* Wd1 = (const float*)d_in[9];
    const float* bd1 = (const float*)d_in[10];
    const float* Wd2 = (const float*)d_in[11];
    const float* bd2 = (const float*)d_in[12];
    const float* Wf1 = (const float*)d_in[13];
    const float* bf1 = (const float*)d_in[14];
    const float* Wf2 = (const float*)d_in[15];
    const float* bf2 = (const float*)d_in[16];
    float* out = (float*)d_out;

    float *h2f, *scr256, *dh;
    cudaGetSymbolAddress((void**)&h2f, g_h2f);
    cudaGetSymbolAddress((void**)&scr256, g_scr256);
    cudaGetSymbolAddress((void**)&dh, g_dh);

    cudaFuncSetAttribute(fused_step_kernel,
                         cudaFuncAttributeMaxDynamicSharedMemorySize, DSMEM_ALLOC);

    setup_kernel<<<1024, 256>>>(Wh1, Wx2, Wh2, Wx1);

    const int M2 = 8 * 28 * 28;   // 6272

    // pipelined schedule: launch k = L1(k) + L2(k-1)
    fused_step_kernel<<<512, 256, DSMEM_ALLOC>>>(0, -1, x, b1, b2);
    for (int k = 1; k < 10; ++k)
        fused_step_kernel<<<736, 256, DSMEM_ALLOC>>>(k, k - 1, x, b1, b2);
    fused_step_kernel<<<224, 256, DSMEM_ALLOC>>>(-1, 9, x, b1, b2);

    dense_relu_kernel<<<(M2 * 256 + 255) / 256, 256>>>(h2f, Wd1, bd1, scr256, M2, 128, 256, 1);
    dense_relu_kernel<<<(M2 * 64 + 255) / 256, 256>>>(scr256, Wd2, bd2, dh, M2, 256, 64, 1);

    final_fc_kernel<<<8 * 30 * 28, 64>>>(dh, tt, loc, Wf1, bf1, Wf2, bf2, out);
}

// round 17
// speedup vs baseline: 2.1539x; 1.0043x over previous
#include <cuda_runtime.h>
#include <cuda_bf16.h>
#include <cstdint>
#include <math.h>

// ---------------------------------------------------------------------------
// Q6Model: 2-layer ConvLSTM (T=10) + dense head + concat + FC head
// Round 17 = R16 + LPT block ordering: long L2(k-1) blocks occupy low
// blockIdx (wave 1), short L1(k) blocks fill behind. Zero arithmetic change.
// ---------------------------------------------------------------------------

#define H1N (8*30*30*256)
#define H2N (8*28*28*128)

__device__ __nv_bfloat16 g_h1b[2][H1N];
__device__ float         g_c1[H1N];
__device__ __nv_bfloat16 g_h2b[2][H2N];
__device__ float         g_c2[H2N];
__device__ float         g_h2f[H2N];
__device__ float g_scr256[8*28*28*256];
__device__ float g_dh[8*28*28*64];
// tile-packed bf16 weights: [nb][kt][tap] tiles of (128 rows x 40 bf16)
__device__ __nv_bfloat16 g_Wt1[8*8*9*5120];
__device__ __nv_bfloat16 g_Wt2x[4*8*9*5120];
__device__ __nv_bfloat16 g_Wt2h[4*4*9*5120];
__device__ float g_Wx1i[9*1024];

// ---------------------------------------------------------------------------
__device__ void pack_tiles_dev(const float* __restrict__ W, __nv_bfloat16* __restrict__ out,
                               int C, int N, int i, int stride)
{
    int ktiles = C / 32;
    int F = N >> 2;
    long total = (long)(N / 128) * 9 * ktiles * 5120;
    for (long e = i; e < total; e += stride) {
        int pos = (int)(e % 40);
        long r2 = e / 40;
        int row = (int)(r2 % 128);
        long tile = r2 / 128;
        int tap = (int)(tile % 9);
        int kt = (int)((tile / 9) % ktiles);
        int nb = (int)(tile / ((long)ktiles * 9));
        __nv_bfloat16 v = __float2bfloat16(0.f);
        if (pos < 32) {
            int np = nb * 128 + row;
            int g = np & 3, f = np >> 2;
            int n = g * F + f;
            v = __float2bfloat16(W[(long)(tap * C + kt * 32 + pos) * N + n]);
        }
        out[e] = v;
    }
}

__global__ void setup_kernel(const float* __restrict__ Wh1, const float* __restrict__ Wx2,
                             const float* __restrict__ Wh2, const float* __restrict__ Wx1)
{
    int i = blockIdx.x * blockDim.x + threadIdx.x;
    int stride = gridDim.x * blockDim.x;
    unsigned* h1u = (unsigned*)g_h1b;
    unsigned* h2u = (unsigned*)g_h2b;
    for (int k = i; k < H1N; k += stride) g_c1[k] = 0.f;
    for (int k = i; k < H1N; k += stride) h1u[k] = 0u;
    for (int k = i; k < H2N; k += stride) g_c2[k] = 0.f;
    for (int k = i; k < H2N; k += stride) h2u[k] = 0u;
    pack_tiles_dev(Wh1, g_Wt1, 256, 1024, i, stride);
    pack_tiles_dev(Wx2, g_Wt2x, 256, 512, i, stride);
    pack_tiles_dev(Wh2, g_Wt2h, 128, 512, i, stride);
    for (int idx = i; idx < 9 * 1024; idx += stride) {
        int n = idx % 1024;
        int t = idx / 1024;
        int np = 4 * (n % 256) + (n / 256);
        g_Wx1i[t * 1024 + np] = Wx1[idx];
    }
}

// ---------------------------------------------------------------------------
__device__ __forceinline__ void mma_bf16(float* d, const unsigned* a, const unsigned* b) {
    asm volatile(
        "mma.sync.aligned.m16n8k16.row.col.f32.bf16.bf16.f32 "
        "{%0,%1,%2,%3}, {%4,%5,%6,%7}, {%8,%9}, {%0,%1,%2,%3};\n"
        : "+f"(d[0]), "+f"(d[1]), "+f"(d[2]), "+f"(d[3])
        : "r"(a[0]), "r"(a[1]), "r"(a[2]), "r"(a[3]), "r"(b[0]), "r"(b[1]));
}

__device__ __forceinline__ void ldsm_x4(unsigned& r0, unsigned& r1, unsigned& r2, unsigned& r3,
                                        unsigned addr) {
    asm volatile("ldmatrix.sync.aligned.m8n8.x4.shared.b16 {%0,%1,%2,%3}, [%4];"
                 : "=r"(r0), "=r"(r1), "=r"(r2), "=r"(r3) : "r"(addr));
}

__device__ __forceinline__ void cp16(unsigned dst, const void* src, int sz) {
    asm volatile("cp.async.cg.shared.global [%0], [%1], 16, %2;"
                 :: "r"(dst), "l"(src), "r"(sz));
}

__device__ __forceinline__ void bulk_ld(unsigned dst, const void* src, unsigned bytes,
                                        unsigned mbar) {
    asm volatile(
        "cp.async.bulk.shared::cluster.global.mbarrier::complete_tx::bytes [%0], [%1], %2, [%3];"
        :: "r"(dst), "l"(src), "r"(bytes), "r"(mbar) : "memory");
}

__device__ __forceinline__ void mbar_init(unsigned mbar, unsigned cnt) {
    asm volatile("mbarrier.init.shared.b64 [%0], %1;" :: "r"(mbar), "r"(cnt) : "memory");
}

__device__ __forceinline__ void mbar_expect_tx(unsigned mbar, unsigned bytes) {
    asm volatile("mbarrier.arrive.expect_tx.shared.b64 _, [%0], %1;"
                 :: "r"(mbar), "r"(bytes) : "memory");
}

__device__ __forceinline__ void mbar_wait(unsigned mbar, unsigned parity) {
    unsigned done;
    asm volatile(
        "{\n\t.reg .pred p;\n\t"
        "mbarrier.try_wait.parity.shared.b64 p, [%1], %2;\n\t"
        "selp.b32 %0, 1, 0, p;\n\t}"
        : "=r"(done) : "r"(mbar), "r"(parity) : "memory");
    if (!done) {
        asm volatile(
            "{\n\t.reg .pred P1;\n\t"
            "WL_%=:\n\t"
            "mbarrier.try_wait.parity.shared.b64 P1, [%0], %1;\n\t"
            "@P1 bra.uni WD_%=;\n\t"
            "bra.uni WL_%=;\n\t"
            "WD_%=:\n\t}"
            :: "r"(mbar), "r"(parity) : "memory");
    }
}

__device__ __forceinline__ float sigmoidf_(float x) { return 1.f / (1.f + expf(-x)); }

// ---------------------------------------------------------------------------
// R14 conv body, verbatim, parameterized on (bx, nb).
// ---------------------------------------------------------------------------
#define HROWB 80
#define HALO_B (192*HROWB)                 // 15360
#define B_TILE 10240
#define B_GROUP (3*B_TILE)                 // 30720
#define BBUF_OFF (2*HALO_B)                // 30720
#define DSMEM_ALLOC (BBUF_OFF + 2*B_GROUP) // 92160
#define SROW 33
#define SG (128*SROW)                      // epilogue: 4*SG*4 = 67584 <= alloc

__device__ void conv_body(
    const __nv_bfloat16* __restrict__ srcA, int CA, int HA, int WA, long sAb, int padA,
    const __nv_bfloat16* __restrict__ WtA, int kt0,
    const __nv_bfloat16* __restrict__ srcB, int CB, int HB, int WB, long sBb, int padB,
    const __nv_bfloat16* __restrict__ WtB, int kt1,
    const float* __restrict__ xsrc, int xW, long xsb,
    const float* __restrict__ WxI, int useX,
    const float* __restrict__ bias,
    __nv_bfloat16* __restrict__ hb, float* __restrict__ hf,
    float* __restrict__ c,
    int OH, int OW, int YT, int N, int bx, int nb)
{
    extern __shared__ char smem[];
    unsigned smem_u = (unsigned)__cvta_generic_to_shared(smem);
    __shared__ __align__(8) unsigned long long s_mbar[2];

    const int tid = threadIdx.x;
    const int n0 = nb * 128;
    const int y0 = (bx % YT) * 4;
    const int pb = bx / YT;
    const unsigned mb0 = (unsigned)__cvta_generic_to_shared(&s_mbar[0]);

    const int wid = tid >> 5, lane = tid & 31;
    const int wm = (wid >> 2) * 64;
    const int wn = (wid & 3) * 32;
    const int g = lane >> 2, tg = lane & 3;

    const int a_lrow = lane & 15;
    const int a_koff = (lane & 16) ? 16 : 0;
    const int b_lrow = (lane & 7) + ((lane & 16) ? 8 : 0);
    const int b_koff = (lane & 8) ? 16 : 0;

    if (tid == 0) {
        mbar_init(mb0, 1);
        mbar_init(mb0 + 8, 1);
    }
    __syncthreads();

    const int ktotal = kt0 + kt1;
    const int G = 3 * ktotal;

    float acc[4][4][4];
#pragma unroll
    for (int mi = 0; mi < 4; ++mi)
#pragma unroll
        for (int ni = 0; ni < 4; ++ni)
#pragma unroll
            for (int r = 0; r < 4; ++r) acc[mi][ni][r] = 0.f;

    auto stage_halo = [&](int gk, int abuf) {
        const __nv_bfloat16* src; int C, H, W, pad, K0; long sb;
        if (gk < kt0) { src = srcA; C = CA; H = HA; W = WA; sb = sAb; pad = padA; K0 = gk * 32; }
        else          { src = srcB; C = CB; H = HB; W = WB; sb = sBb; pad = padB; K0 = (gk - kt0) * 32; }
#pragma unroll
        for (int i = 0; i < 3; ++i) {
            int idx = tid + i * 256;
            int hr = idx >> 2, q = idx & 3;
            int h = hr >> 5, cx = hr & 31;
            int y = y0 - pad + h;
            int xx = cx - pad;
            bool ok = ((unsigned)y < (unsigned)H) && ((unsigned)xx < (unsigned)W);
            const __nv_bfloat16* sp = ok
                ? src + (long)pb * sb + ((long)y * W + xx) * C + K0 + q * 8
                : src;
            cp16(smem_u + abuf * HALO_B + hr * HROWB + q * 16, sp, ok ? 16 : 0);
        }
    };

    auto issueB = [&](int gq) {
        if (tid == 0) {
            int gg = gq / 3, tr = gq - gg * 3;
            const __nv_bfloat16* Wt; int ktn, ktl;
            if (gg < kt0) { Wt = WtA; ktn = kt0; ktl = gg; }
            else          { Wt = WtB; ktn = kt1; ktl = gg - kt0; }
            const __nv_bfloat16* bt = Wt + (long)((nb * ktn + ktl) * 9 + tr * 3) * 5120;
            unsigned mb = mb0 + (gq & 1) * 8;
            mbar_expect_tx(mb, B_GROUP);
            bulk_ld(smem_u + BBUF_OFF + (gq & 1) * B_GROUP, bt, B_GROUP, mb);
        }
    };

    auto compute = [&](int abuf, int tshift, unsigned Bb) {
        unsigned Ab = smem_u + abuf * HALO_B + (unsigned)(tshift * HROWB);
#pragma unroll
        for (int ks = 0; ks < 2; ++ks) {
            unsigned a[4][4];
#pragma unroll
            for (int mi = 0; mi < 4; ++mi)
                ldsm_x4(a[mi][0], a[mi][1], a[mi][2], a[mi][3],
                        Ab + (unsigned)((wm + mi * 16 + a_lrow) * HROWB + a_koff + ks * 32));
            unsigned b[4][2];
#pragma unroll
            for (int np = 0; np < 2; ++np) {
                unsigned r0, r1, r2, r3;
                ldsm_x4(r0, r1, r2, r3,
                        Bb + (unsigned)((wn + np * 16 + b_lrow) * HROWB + b_koff + ks * 32));
                b[2 * np][0] = r0; b[2 * np][1] = r1;
                b[2 * np + 1][0] = r2; b[2 * np + 1][1] = r3;
            }
#pragma unroll
            for (int mi = 0; mi < 4; ++mi)
#pragma unroll
                for (int ni = 0; ni < 4; ++ni)
                    mma_bf16(acc[mi][ni], a[mi], b[ni]);
        }
    };

    // ---- prologue ----
    issueB(0);
    issueB(1);
    stage_halo(0, 0);
    asm volatile("cp.async.commit_group;");

    // ---- main loop over 3-tap groups ----
    for (int gq = 0; gq < G; ++gq) {
        int gk = gq / 3, tr = gq - gk * 3;
        if (tid == 0) mbar_wait(mb0 + (gq & 1) * 8, (gq >> 1) & 1);
        __syncthreads();          // B(gq) visible; compute(gq-1) done everywhere
        if (gq >= 1 && gq + 1 < G) issueB(gq + 1);
        if (tr == 0) {
            if (gk + 1 < ktotal) {
                stage_halo(gk + 1, (gk + 1) & 1);
                asm volatile("cp.async.commit_group;");
                asm volatile("cp.async.wait_group 1;");   // OWN halo(gk) copies landed
            } else {
                asm volatile("cp.async.wait_group 0;");
            }
            __syncthreads();      // ALL threads' halo(gk) copies landed & visible
        }
        unsigned Bg = smem_u + BBUF_OFF + (gq & 1) * B_GROUP;
#pragma unroll
        for (int i = 0; i < 3; ++i) {
            compute(gk & 1, tr * 32 + i, Bg + i * B_TILE);
        }
    }

    // ---- fp32 epilogue for the C=1 input conv (layer 1 only), interleaved W
    if (useX) {
        int eply[8], eplx[8];
        bool ev[8];
#pragma unroll
        for (int e = 0; e < 8; ++e) {
            int rr = wm + (e >> 1) * 16 + g + (e & 1) * 8;
            int ly = rr >> 5, lx = rr & 31;
            ev[e] = (lx < OW) && (y0 + ly < OH);
            eply[e] = y0 + ly; eplx[e] = lx;
        }
        for (int tap = 0; tap < 9; ++tap) {
            int dy = tap / 3, dx = tap % 3;
            float wv[4][2];
#pragma unroll
            for (int ni = 0; ni < 4; ++ni) {
                int col = n0 + wn + ni * 8 + 2 * tg;
                wv[ni][0] = WxI[tap * N + col];
                wv[ni][1] = WxI[tap * N + col + 1];
            }
#pragma unroll
            for (int e = 0; e < 8; ++e) if (ev[e]) {
                float xv = xsrc[(long)pb * xsb + (long)(eply[e] + dy) * xW + (eplx[e] + dx)];
#pragma unroll
                for (int ni = 0; ni < 4; ++ni) {
                    acc[e >> 1][ni][(e & 1) * 2 + 0] = fmaf(xv, wv[ni][0], acc[e >> 1][ni][(e & 1) * 2 + 0]);
                    acc[e >> 1][ni][(e & 1) * 2 + 1] = fmaf(xv, wv[ni][1], acc[e >> 1][ni][(e & 1) * 2 + 1]);
                }
            }
        }
    }

    // ---- fused LSTM epilogue ----
    __syncthreads();
    float* S = (float*)smem;
#pragma unroll
    for (int mi = 0; mi < 4; ++mi) {
#pragma unroll
        for (int ni = 0; ni < 4; ++ni) {
            int c0 = wn + ni * 8 + 2 * tg;
            int c1 = c0 + 1;
            int r0 = wm + mi * 16 + g;
            int r1 = r0 + 8;
            S[(c0 & 3) * SG + r0 * SROW + (c0 >> 2)] = acc[mi][ni][0];
            S[(c1 & 3) * SG + r0 * SROW + (c1 >> 2)] = acc[mi][ni][1];
            S[(c0 & 3) * SG + r1 * SROW + (c0 >> 2)] = acc[mi][ni][2];
            S[(c1 & 3) * SG + r1 * SROW + (c1 >> 2)] = acc[mi][ni][3];
        }
    }
    __syncthreads();

    {
        const int F = N >> 2;
        const int f0 = nb * 32;
        const int fl = tid & 31;
        const int rbase = (tid >> 5) * 16;
        const int fg = f0 + fl;
        const float bi = bias[fg];
        const float bfr = bias[F + fg];
        const float bc = bias[2 * F + fg];
        const float bo = bias[3 * F + fg];
#pragma unroll 4
        for (int rr = 0; rr < 16; ++rr) {
            int r = rbase + rr;
            int ly = r >> 5, lx = r & 31;
            if (lx < OW && y0 + ly < OH) {
                float zi = S[0 * SG + r * SROW + fl] + bi;
                float zf = S[1 * SG + r * SROW + fl] + bfr;
                float zc = S[2 * SG + r * SROW + fl] + bc;
                float zo = S[3 * SG + r * SROW + fl] + bo;
                long gm = (long)pb * OH * OW + (long)(y0 + ly) * OW + lx;
                long ci = gm * F + fg;
                float cn = sigmoidf_(zf) * c[ci] + sigmoidf_(zi) * tanhf(zc);
                float hn = sigmoidf_(zo) * tanhf(cn);
                c[ci] = cn;
                hb[ci] = __float2bfloat16(hn);
                if (hf) hf[ci] = hn;
            }
        }
    }
}

// ---------------------------------------------------------------------------
// Fused step, LPT ordering: blocks [0, nL2) run L2(tsB) (long blocks first);
// blocks [nL2, nL2+nL1) run L1(tsA). Deps via launch boundaries.
// ---------------------------------------------------------------------------
__global__ __launch_bounds__(256)
void fused_step_kernel(int tsA, int tsB,
                       const float* __restrict__ x,
                       const float* __restrict__ b1,
                       const float* __restrict__ b2)
{
    const int nL2 = (tsB >= 0) ? 224 : 0;
    const int bid = blockIdx.x;
    if (bid < nL2) {
        // L2 at tsB: input conv (h1(tsB), 30x30 VALID) + recurrent (h2 prev, SAME)
        int bx = bid % 56, nb = bid / 56;
        int p = tsB & 1;
        const __nv_bfloat16* h1w = p ? g_h1b[0] : g_h1b[1];   // h1 output at tsB
        const __nv_bfloat16* h2r = p ? g_h2b[1] : g_h2b[0];
        __nv_bfloat16* h2w = p ? g_h2b[0] : g_h2b[1];
        conv_body(h1w, 256, 30, 30, (long)30 * 30 * 256, 0, g_Wt2x, /*kt0=*/8,
                  h2r, 128, 28, 28, (long)28 * 28 * 128, 1, g_Wt2h, /*kt1=*/4,
                  x, 32, (long)10 * 32 * 32, g_Wx1i, /*useX=*/0,
                  b2, h2w, g_h2f, g_c2,
                  /*OH=*/28, /*OW=*/28, /*YT=*/7, /*N=*/512, bx, nb);
    } else {
        // L1 at tsA: recurrent conv (h1 prev, 30x30 SAME, C=256) + x epilogue
        int lb = bid - nL2;
        int bx = lb & 63, nb = lb >> 6;
        int p = tsA & 1;
        const __nv_bfloat16* h1r = p ? g_h1b[1] : g_h1b[0];
        __nv_bfloat16* h1w = p ? g_h1b[0] : g_h1b[1];
        conv_body(h1r, 256, 30, 30, (long)30 * 30 * 256, 1, g_Wt1, /*kt0=*/0,
                  h1r, 256, 30, 30, (long)30 * 30 * 256, 1, g_Wt1, /*kt1=*/8,
                  x + (long)tsA * 32 * 32, 32, (long)10 * 32 * 32, g_Wx1i, /*useX=*/1,
                  b1, h1w, nullptr, g_c1,
                  /*OH=*/30, /*OW=*/30, /*YT=*/8, /*N=*/1024, bx, nb);
    }
}

// ---------------------------------------------------------------------------
__global__ void dense_relu_kernel(const float* __restrict__ in,
                                  const float* __restrict__ W,
                                  const float* __restrict__ bias,
                                  float* __restrict__ out,
                                  int M, int K, int N, int do_relu)
{
    int idx = blockIdx.x * blockDim.x + threadIdx.x;
    if (idx >= M * N) return;
    int m = idx / N, n = idx % N;
    const float* ip = in + (long)m * K;
    float s = bias[n];
    for (int k = 0; k < K; ++k) s = fmaf(ip[k], W[k * N + n], s);
    if (do_relu) s = fmaxf(s, 0.f);
    out[idx] = s;
}

// ---------------------------------------------------------------------------
__global__ void final_fc_kernel(const float* __restrict__ dh,
                                const float* __restrict__ tin,
                                const float* __restrict__ locin,
                                const float* __restrict__ Wf1,
                                const float* __restrict__ bf1,
                                const float* __restrict__ Wf2,
                                const float* __restrict__ bf2,
                                float* __restrict__ out)
{
    int blk = blockIdx.x;              // = (b*30 + r)*28 + w
    int w = blk % 28;
    int r = (blk / 28) % 30;
    int b = blk / (28 * 30);

    __shared__ float v[64];
    __shared__ float red[64];
    int j = threadIdx.x;

    const float* src;
    if (r < 28)       src = dh    + (((long)(b * 28 + r)) * 28 + w) * 64;
    else if (r == 28) src = tin   + ((long)b * 28 + w) * 64;
    else              src = locin + ((long)b * 28 + w) * 64;
    v[j] = src[j];
    __syncthreads();

    float s = bf1[j];
#pragma unroll
    for (int k = 0; k < 64; ++k) s = fmaf(v[k], Wf1[k * 64 + j], s);
    s = fmaxf(s, 0.f) * Wf2[j];
    red[j] = s;
    __syncthreads();
    for (int off = 32; off > 0; off >>= 1) {
        if (j < off) red[j] += red[j + off];
        __syncthreads();
    }
    if (j == 0) out[blk] = red[0] + bf2[0];
}

// ---------------------------------------------------------------------------
extern "C" void kernel_launch(void* const* d_in, const int* in_sizes, int n_in,
                              void* d_out, int out_size)
{
    const float* x   = (const float*)d_in[0];
    const float* tt  = (const float*)d_in[1];
    const float* loc = (const float*)d_in[2];
    const float* Wx1 = (const float*)d_in[3];
    const float* Wh1 = (const float*)d_in[4];
    const float* b1  = (const float*)d_in[5];
    const float* Wx2 = (const float*)d_in[6];
    const float* Wh2 = (const float*)d_in[7];
    const float* b2  = (const float*)d_in[8];
    const float* Wd1 = (const float*)d_in[9];
    const float* bd1 = (const float*)d_in[10];
    const float* Wd2 = (const float*)d_in[11];
    const float* bd2 = (const float*)d_in[12];
    const float* Wf1 = (const float*)d_in[13];
    const float* bf1 = (const float*)d_in[14];
    const float* Wf2 = (const float*)d_in[15];
    const float* bf2 = (const float*)d_in[16];
    float* out = (float*)d_out;

    float *h2f, *scr256, *dh;
    cudaGetSymbolAddress((void**)&h2f, g_h2f);
    cudaGetSymbolAddress((void**)&scr256, g_scr256);
    cudaGetSymbolAddress((void**)&dh, g_dh);

    cudaFuncSetAttribute(fused_step_kernel,
                         cudaFuncAttributeMaxDynamicSharedMemorySize, DSMEM_ALLOC);

    setup_kernel<<<1024, 256>>>(Wh1, Wx2, Wh2, Wx1);

    const int M2 = 8 * 28 * 28;   // 6272

    // pipelined schedule: launch k = L2(k-1) [long, first] + L1(k) [short]
    fused_step_kernel<<<512, 256, DSMEM_ALLOC>>>(0, -1, x, b1, b2);
    for (int k = 1; k < 10; ++k)
        fused_step_kernel<<<736, 256, DSMEM_ALLOC>>>(k, k - 1, x, b1, b2);
    fused_step_kernel<<<224, 256, DSMEM_ALLOC>>>(-1, 9, x, b1, b2);

    dense_relu_kernel<<<(M2 * 256 + 255) / 256, 256>>>(h2f, Wd1, bd1, scr256, M2, 128, 256, 1);
    dense_relu_kernel<<<(M2 * 64 + 255) / 256, 256>>>(scr256, Wd2, bd2, dh, M2, 256, 64, 1);

    final_fc_kernel<<<8 * 30 * 28, 64>>>(dh, tt, loc, Wf1, bf1, Wf2, bf2, out);
}